// round 10
// baseline (speedup 1.0000x reference)
#include <cuda_runtime.h>
#include <cuda_fp16.h>
#include <math.h>
#include <stdint.h>

#define NM    16384
#define NSd   512
#define NIN   64
#define NOUT  64
#define MAXITER   200
#define EPS_STOP  1e-3f

#define GRID_IT   128
#define NTH_IT    512                  // 16 warps
#define KC        64                   // K (halves) per B chunk
#define NCHUNK    8                    // 512 / 64
#define LDH       72                   // B stage row pitch (halves)
#define LDB       (LDH * 2)            // 144 B
#define BSTAGE    (256 * LDB)          // 36864 B per stage
#define Z_LDH     520                  // z row pitch halves (1040 B)
#define Z_BYTES   (128 * Z_LDH * 2)    // 133120 B
#define SMEM_DYN  (Z_BYTES + 2 * BSTAGE)   // 206848 B
#define XP        400                  // composite-x smem pitch bytes (200 words ≡ 4 mod 32)

// ---------------- device scratch ----------------
__device__ float  g_xA[NM * NSd];          // x@A^T + b (fp32)
__device__ __half g_xC[NM * 192];          // [x_hi | x_lo | x_hi] per row
__device__ __half g_AC[NSd * 192];         // [A_hi | A_hi | A_lo] per row
__device__ __half g_BmH[NSd * NSd];        // fp16 Bm  (rows n, cols k)
__device__ __half g_BmTH[NSd * NSd];       // fp16 Bm^T
__device__ __half g_WhH[NOUT * NSd];       // Wh hi
__device__ __half g_WhL[NOUT * NSd];       // Wh lo
__device__ volatile unsigned g_ecnt[256];  // per-epoch arrival counters
__device__ float g_part[2][2 * GRID_IT];
__device__ float g_jacpart[GRID_IT];

// ---------------- helpers ----------------
__device__ __forceinline__ uint32_t smem_u32(const void* p) {
    uint32_t a;
    asm("{ .reg .u64 t; cvta.to.shared.u64 t, %1; cvt.u32.u64 %0, t; }" : "=r"(a) : "l"(p));
    return a;
}
__device__ __forceinline__ float tanh_ap(float x) {
    float y; asm("tanh.approx.f32 %0, %1;" : "=f"(y) : "f"(x)); return y;
}
__device__ __forceinline__ void cp_async16(uint32_t saddr, const void* g) {
    asm volatile("cp.async.cg.shared.global [%0], [%1], 16;" :: "r"(saddr), "l"(g) : "memory");
}
__device__ __forceinline__ void ldmatrix_x4(uint32_t r[4], uint32_t addr) {
    asm volatile("ldmatrix.sync.aligned.m8n8.x4.shared.b16 {%0,%1,%2,%3}, [%4];"
        : "=r"(r[0]), "=r"(r[1]), "=r"(r[2]), "=r"(r[3]) : "r"(addr));
}
__device__ __forceinline__ void mma_f16(float c[4], const uint32_t a[4], const uint32_t b[2]) {
    asm volatile(
        "mma.sync.aligned.m16n8k16.row.col.f32.f16.f16.f32 "
        "{%0,%1,%2,%3}, {%4,%5,%6,%7}, {%8,%9}, {%0,%1,%2,%3};"
        : "+f"(c[0]), "+f"(c[1]), "+f"(c[2]), "+f"(c[3])
        : "r"(a[0]), "r"(a[1]), "r"(a[2]), "r"(a[3]), "r"(b[0]), "r"(b[1]));
}

// Fused deterministic block reduce of two floats (shuffle + 16-partial broadcast).
__device__ __forceinline__ float2 block_reduce2(float a, float b) {
    __shared__ float2 sr[16];
#pragma unroll
    for (int o = 16; o > 0; o >>= 1) {
        a += __shfl_xor_sync(0xFFFFFFFFu, a, o);
        b += __shfl_xor_sync(0xFFFFFFFFu, b, o);
    }
    const int w = threadIdx.x >> 5, lane = threadIdx.x & 31;
    __syncthreads();
    if (lane == 0) sr[w] = make_float2(a, b);
    __syncthreads();
    float2 t = make_float2(0.f, 0.f);
#pragma unroll
    for (int i = 0; i < 16; ++i) { t.x += sr[i].x; t.y += sr[i].y; }
    return t;
}

// ---------------- fp16 mma pass, A resident in SMEM ----------------
// acc[128x256] = Aop(128 x NC*64 @ aBase, pitch aPitchB) @ Brows(256 x NC*64)^T
template<int NC, bool SYNC>
__device__ void mma_pass(uint32_t aBase, int aPitchB,
                         const __half* __restrict__ Brows, int bStrideH,
                         uint32_t bb, float acc[4][4][4]) {
    const int tid = threadIdx.x;
    const int w = tid >> 5, lane = tid & 31;
    const int wr = w >> 3, wc = w & 7;

#pragma unroll
    for (int f = 0; f < 4; ++f)
#pragma unroll
        for (int g = 0; g < 4; ++g)
#pragma unroll
            for (int r = 0; r < 4; ++r) acc[f][g][r] = 0.f;

    if (SYNC) __syncthreads();

    const int lrow = tid >> 3, lseg = tid & 7;

    auto load_chunk = [&](int c, int stage) {
        const uint32_t sb = bb + (uint32_t)(stage * BSTAGE);
        const int k0 = c * KC;
#pragma unroll
        for (int i = 0; i < 4; ++i) {
            const int row = i * 64 + lrow;
            cp_async16(sb + (uint32_t)(row * LDB + lseg * 16),
                       Brows + (size_t)row * bStrideH + k0 + lseg * 8);
        }
        asm volatile("cp.async.commit_group;" ::: "memory");
    };

    load_chunk(0, 0);

    const int rsel = lane & 15;
    const int ksel = (lane >> 4) << 3;
    const uint32_t arow = aBase + (uint32_t)((wr * 64 + rsel) * aPitchB);

    for (int c = 0; c < NC; ++c) {
        asm volatile("cp.async.wait_group 0;" ::: "memory");
        __syncthreads();
        if (c + 1 < NC) load_chunk(c + 1, (c + 1) & 1);

        const uint32_t sB = bb + (uint32_t)((c & 1) * BSTAGE);
#pragma unroll
        for (int ks = 0; ks < 4; ++ks) {
            const uint32_t koff = (uint32_t)((ks * 16 + ksel) * 2);
            const uint32_t akoff = (uint32_t)(c * (KC * 2)) + koff;
            uint32_t a[4][4], bf[2][4];
#pragma unroll
            for (int f = 0; f < 4; ++f)
                ldmatrix_x4(a[f], arow + (uint32_t)(f * 16 * aPitchB) + akoff);
#pragma unroll
            for (int h = 0; h < 2; ++h)
                ldmatrix_x4(bf[h], sB + (uint32_t)((wc * 32 + h * 16 + rsel) * LDB) + koff);
#pragma unroll
            for (int f = 0; f < 4; ++f) {
                { uint32_t b2[2] = {bf[0][0], bf[0][2]}; mma_f16(acc[f][0], a[f], b2); }
                { uint32_t b2[2] = {bf[0][1], bf[0][3]}; mma_f16(acc[f][1], a[f], b2); }
                { uint32_t b2[2] = {bf[1][0], bf[1][2]}; mma_f16(acc[f][2], a[f], b2); }
                { uint32_t b2[2] = {bf[1][1], bf[1][3]}; mma_f16(acc[f][3], a[f], b2); }
            }
        }
    }
}

// ---------------- y pass: acc[128x64] (+)= Z(128x512) @ Wh(64x512)^T ----------------
template<bool ZERO, bool SYNC>
__device__ void mma_pass_y(uint32_t zb, const __half* __restrict__ Brows,
                           uint32_t bb, float acc[4][4]) {
    const int tid = threadIdx.x;
    const int w = tid >> 5, lane = tid & 31;
    const int wm = w >> 1, wn = w & 1;
    if (ZERO) {
#pragma unroll
        for (int g = 0; g < 4; ++g)
#pragma unroll
            for (int r = 0; r < 4; ++r) acc[g][r] = 0.f;
    }
    if (SYNC) __syncthreads();
    const int brow = tid >> 3, bseg = tid & 7;   // 64 rows x 8 segs
    auto load_chunk = [&](int c, int stage) {
        const uint32_t sb = bb + (uint32_t)(stage * BSTAGE);
        cp_async16(sb + (uint32_t)(brow * LDB + bseg * 16),
                   Brows + (size_t)brow * NSd + c * KC + bseg * 8);
        asm volatile("cp.async.commit_group;" ::: "memory");
    };
    load_chunk(0, 0);
    const int rsel = lane & 15;
    const int ksel = (lane >> 4) << 3;
    const uint32_t arow = zb + (uint32_t)((wm * 16 + rsel) * (Z_LDH * 2));
    for (int c = 0; c < NCHUNK; ++c) {
        asm volatile("cp.async.wait_group 0;" ::: "memory");
        __syncthreads();
        if (c + 1 < NCHUNK) load_chunk(c + 1, (c + 1) & 1);
        const uint32_t sB = bb + (uint32_t)((c & 1) * BSTAGE);
#pragma unroll
        for (int ks = 0; ks < 4; ++ks) {
            const uint32_t koff = (uint32_t)((ks * 16 + ksel) * 2);
            uint32_t a[4], bf[2][4];
            ldmatrix_x4(a, arow + (uint32_t)(c * (KC * 2)) + koff);
#pragma unroll
            for (int h = 0; h < 2; ++h)
                ldmatrix_x4(bf[h], sB + (uint32_t)((wn * 32 + h * 16 + rsel) * LDB) + koff);
            { uint32_t b2[2] = {bf[0][0], bf[0][2]}; mma_f16(acc[0], a, b2); }
            { uint32_t b2[2] = {bf[0][1], bf[0][3]}; mma_f16(acc[1], a, b2); }
            { uint32_t b2[2] = {bf[1][0], bf[1][2]}; mma_f16(acc[2], a, b2); }
            { uint32_t b2[2] = {bf[1][1], bf[1][3]}; mma_f16(acc[3], a, b2); }
        }
    }
}

// ---------------- kernels ----------------
// Input conversions (hi/lo splits) + epoch-counter init. 4096 x 256.
__global__ void k_prep(const float* __restrict__ x,
                       const float* __restrict__ Bm,
                       const float* __restrict__ A,
                       const float* __restrict__ Wh) {
    const int gid = blockIdx.x * 256 + threadIdx.x;   // 0..1048575
    {
        const float xv = x[gid];
        const __half hi = __float2half_rn(xv);
        const __half lo = __float2half_rn(xv - __half2float(hi));
        const int r = gid >> 6, c = gid & 63;
        g_xC[r * 192 + c]        = hi;
        g_xC[r * 192 + 64 + c]   = lo;
        g_xC[r * 192 + 128 + c]  = hi;
    }
    if (gid < NSd * NSd) {
        const __half h = __float2half_rn(Bm[gid]);
        g_BmH[gid] = h;
        const int i = gid >> 9, j = gid & 511;
        g_BmTH[j * NSd + i] = h;
    }
    if (gid < NSd * NIN) {
        const float av = A[gid];
        const __half hi = __float2half_rn(av);
        const __half lo = __float2half_rn(av - __half2float(hi));
        const int n = gid >> 6, k = gid & 63;
        g_AC[n * 192 + k]       = hi;
        g_AC[n * 192 + 64 + k]  = hi;
        g_AC[n * 192 + 128 + k] = lo;
    }
    if (gid < NOUT * NSd) {
        const float wv = Wh[gid];
        const __half hi = __float2half_rn(wv);
        g_WhH[gid] = hi;
        g_WhL[gid] = __float2half_rn(wv - __half2float(hi));
    }
    if (gid < 256) g_ecnt[gid] = 0u;
}

// Persistent solver: split-fp16 xA, lagged-stop iterations, fused y + g + vjp + jac.
__global__ void __launch_bounds__(NTH_IT, 1) k_iter(const float* __restrict__ bvec,
                                                    const float* __restrict__ v,
                                                    const float* __restrict__ bhv,
                                                    float* __restrict__ out) {
    extern __shared__ __half smh[];
    const uint32_t zb = smem_u32(smh);
    const uint32_t bb = zb + (uint32_t)Z_BYTES;
    const int tid = threadIdx.x;
    const int w = tid >> 5, lane = tid & 31;
    const int wr = w >> 3, wc = w & 7;
    const int grp = lane >> 2, tg = lane & 3;
    const int m0 = blockIdx.x * 128;
    float acc[4][4][4];
    uint32_t stash[32];

    const int mbase = wr * 64 + grp;
    float* xaRow = g_xA + (size_t)(m0 + mbase) * NSd;
    const float* vRow = v + (size_t)(m0 + mbase) * NSd;

    // ---- xA phase: composite x (K=192) -> exact-grade xA; z1 = tanh(xA) ----
    {
        for (int o = tid; o < 3072; o += NTH_IT) {            // 128 rows x 24 segs
            const int row = o / 24, seg = o - row * 24;
            cp_async16(zb + (uint32_t)(row * XP + seg * 16),
                       g_xC + (size_t)(m0 + row) * 192 + seg * 8);
        }
        asm volatile("cp.async.commit_group;" ::: "memory");

        mma_pass<3, true>(zb, XP, g_AC, 192, bb, acc);
#pragma unroll
        for (int f = 0; f < 4; ++f) {
#pragma unroll
            for (int g = 0; g < 4; ++g) {
                const int n = wc * 32 + g * 8 + tg * 2;
                float2 b2 = *(const float2*)&bvec[n];
#pragma unroll
                for (int hr = 0; hr < 2; ++hr) {
                    const int off = (f * 16 + hr * 8) * NSd + n;
                    const float xx = acc[f][g][hr * 2 + 0] + b2.x;
                    const float xy = acc[f][g][hr * 2 + 1] + b2.y;
                    *(float2*)&xaRow[off] = make_float2(xx, xy);
                    __half2 hh = __halves2half2(__float2half_rn(tanh_ap(xx)),
                                                __float2half_rn(tanh_ap(xy)));
                    stash[(f * 4 + g) * 2 + hr] = *reinterpret_cast<uint32_t*>(&hh);
                }
            }
        }
        mma_pass<3, true>(zb, XP, g_AC + (size_t)256 * 192, 192, bb, acc);
        __syncthreads();   // pass-1 GEMM reads of x-tile done -> overwrite with z
#pragma unroll
        for (int f = 0; f < 4; ++f) {
#pragma unroll
            for (int g = 0; g < 4; ++g) {
                const int n = wc * 32 + g * 8 + tg * 2;
                float2 b2 = *(const float2*)&bvec[256 + n];
#pragma unroll
                for (int hr = 0; hr < 2; ++hr) {
                    const int ml = mbase + f * 16 + hr * 8;
                    const int off = (f * 16 + hr * 8) * NSd + 256 + n;
                    const float xx = acc[f][g][hr * 2 + 0] + b2.x;
                    const float xy = acc[f][g][hr * 2 + 1] + b2.y;
                    *(float2*)&xaRow[off] = make_float2(xx, xy);
                    *(__half2*)&smh[ml * Z_LDH + 256 + n] =
                        __halves2half2(__float2half_rn(tanh_ap(xx)),
                                       __float2half_rn(tanh_ap(xy)));
                    *(__half2*)&smh[ml * Z_LDH + n] =
                        *reinterpret_cast<__half2*>(&stash[(f * 4 + g) * 2 + hr]);
                }
            }
        }
    }

    // ---- iterations t = 2..MAXITER with one-iteration-lagged stopping ----
    for (int t = 2; t <= MAXITER; ++t) {
        float lnum = 0.f, lden = 0.f;

        mma_pass<NCHUNK, true>(zb, Z_LDH * 2, g_BmH, NSd, bb, acc);
#pragma unroll
        for (int f = 0; f < 4; ++f) {
#pragma unroll
            for (int g = 0; g < 4; ++g) {
                const int n = wc * 32 + g * 8 + tg * 2;
#pragma unroll
                for (int hr = 0; hr < 2; ++hr) {
                    const int ml = mbase + f * 16 + hr * 8;
                    float2 xa = *(const float2*)&xaRow[(f * 16 + hr * 8) * NSd + n];
                    __half hx = __float2half_rn(tanh_ap(xa.x + acc[f][g][hr * 2 + 0]));
                    __half hy = __float2half_rn(tanh_ap(xa.y + acc[f][g][hr * 2 + 1]));
                    const float zx = __half2float(hx), zy = __half2float(hy);
                    __half2 zp = *(__half2*)&smh[ml * Z_LDH + n];
                    const float dx = zx - __low2float(zp);
                    const float dy = zy - __high2float(zp);
                    lnum += dx * dx + dy * dy;
                    lden += zx * zx + zy * zy;
                    __half2 hh = __halves2half2(hx, hy);
                    stash[(f * 4 + g) * 2 + hr] = *reinterpret_cast<uint32_t*>(&hh);
                }
            }
        }
        mma_pass<NCHUNK, false>(zb, Z_LDH * 2, g_BmH + (size_t)256 * NSd, NSd, bb, acc);
        __syncthreads();   // GEMM reads of z done -> overwrite
#pragma unroll
        for (int f = 0; f < 4; ++f) {
#pragma unroll
            for (int g = 0; g < 4; ++g) {
                const int n = wc * 32 + g * 8 + tg * 2;
#pragma unroll
                for (int hr = 0; hr < 2; ++hr) {
                    const int ml = mbase + f * 16 + hr * 8;
                    const int n2 = 256 + n;
                    float2 xa = *(const float2*)&xaRow[(f * 16 + hr * 8) * NSd + n2];
                    __half hx = __float2half_rn(tanh_ap(xa.x + acc[f][g][hr * 2 + 0]));
                    __half hy = __float2half_rn(tanh_ap(xa.y + acc[f][g][hr * 2 + 1]));
                    const float zx = __half2float(hx), zy = __half2float(hy);
                    __half2 zp = *(__half2*)&smh[ml * Z_LDH + n2];
                    const float dx = zx - __low2float(zp);
                    const float dy = zy - __high2float(zp);
                    lnum += dx * dx + dy * dy;
                    lden += zx * zx + zy * zy;
                    *(__half2*)&smh[ml * Z_LDH + n2] = __halves2half2(hx, hy);
                    *(__half2*)&smh[ml * Z_LDH + n] =
                        *reinterpret_cast<__half2*>(&stash[(f * 4 + g) * 2 + hr]);
                }
            }
        }

        float2 bpart = block_reduce2(lnum, lden);
        if (tid == 0) {
            g_part[t & 1][2 * blockIdx.x]     = bpart.x;
            g_part[t & 1][2 * blockIdx.x + 1] = bpart.y;
            __threadfence();
            if (t > 2) {
                while (g_ecnt[t - 1] < (unsigned)GRID_IT) { }
                __threadfence();
            }
        }
        __syncthreads();

        bool stop = false;
        if (t > 2) {
            float pn = 0.f, pd = 0.f;
            if (tid < GRID_IT) {
                float2 pp = __ldcg((const float2*)&g_part[(t - 1) & 1][2 * tid]);
                pn = pp.x; pd = pp.y;
            }
            float2 tot = block_reduce2(pn, pd);
            const float res = sqrtf(tot.x) / (sqrtf(tot.y) + 1e-8f);
            stop = (res <= EPS_STOP);
        }
        __syncthreads();                       // all reads of slot (t-1)&1 done
        if (tid == 0) atomicAdd((unsigned*)(g_ecnt + t), 1u);
        if (stop) break;
    }

    // ---- y = z* @ Wh^T + bh (exact hi/lo split), written directly to out ----
    {
        float yacc[4][4];
        mma_pass_y<true,  true >(zb, g_WhH, bb, yacc);
        mma_pass_y<false, false>(zb, g_WhL, bb, yacc);
        const int wm = w >> 1, wn = w & 1;
#pragma unroll
        for (int g = 0; g < 4; ++g) {
            const int col = wn * 32 + g * 8 + tg * 2;
            float2 b2 = *(const float2*)&bhv[col];
#pragma unroll
            for (int hr = 0; hr < 2; ++hr) {
                const int m = m0 + wm * 16 + grp + hr * 8;
                *(float2*)&out[(size_t)m * NOUT + col] =
                    make_float2(yacc[g][hr * 2] + b2.x, yacc[g][hr * 2 + 1] + b2.y);
            }
        }
    }

    // ---- g-phase: g = v * (1 - tanh(xA + z* @ Bm^T)^2); overwrite z with g ----
    mma_pass<NCHUNK, false>(zb, Z_LDH * 2, g_BmH, NSd, bb, acc);
#pragma unroll
    for (int f = 0; f < 4; ++f) {
#pragma unroll
        for (int g = 0; g < 4; ++g) {
            const int n = wc * 32 + g * 8 + tg * 2;
#pragma unroll
            for (int hr = 0; hr < 2; ++hr) {
                const int off = (f * 16 + hr * 8) * NSd + n;
                float2 xa = *(const float2*)&xaRow[off];
                float2 vv = *(const float2*)&vRow[off];
                float th;
                th = tanh_ap(xa.x + acc[f][g][hr * 2 + 0]);
                __half gx = __float2half_rn(vv.x * (1.f - th * th));
                th = tanh_ap(xa.y + acc[f][g][hr * 2 + 1]);
                __half gy = __float2half_rn(vv.y * (1.f - th * th));
                __half2 hh = __halves2half2(gx, gy);
                stash[(f * 4 + g) * 2 + hr] = *reinterpret_cast<uint32_t*>(&hh);
            }
        }
    }
    mma_pass<NCHUNK, false>(zb, Z_LDH * 2, g_BmH + (size_t)256 * NSd, NSd, bb, acc);
    __syncthreads();
#pragma unroll
    for (int f = 0; f < 4; ++f) {
#pragma unroll
        for (int g = 0; g < 4; ++g) {
            const int n = wc * 32 + g * 8 + tg * 2;
#pragma unroll
            for (int hr = 0; hr < 2; ++hr) {
                const int ml = mbase + f * 16 + hr * 8;
                const int n2 = 256 + n;
                const int off = (f * 16 + hr * 8) * NSd + n2;
                float2 xa = *(const float2*)&xaRow[off];
                float2 vv = *(const float2*)&vRow[off];
                float th;
                th = tanh_ap(xa.x + acc[f][g][hr * 2 + 0]);
                __half gx = __float2half_rn(vv.x * (1.f - th * th));
                th = tanh_ap(xa.y + acc[f][g][hr * 2 + 1]);
                __half gy = __float2half_rn(vv.y * (1.f - th * th));
                *(__half2*)&smh[ml * Z_LDH + n2] = __halves2half2(gx, gy);
                *(__half2*)&smh[ml * Z_LDH + n] =
                    *reinterpret_cast<__half2*>(&stash[(f * 4 + g) * 2 + hr]);
            }
        }
    }

    // ---- vjp: vJ = g @ Bm ; sum of squares ----
    float ls = 0.f;
    mma_pass<NCHUNK, true>(zb, Z_LDH * 2, g_BmTH, NSd, bb, acc);
#pragma unroll
    for (int f = 0; f < 4; ++f)
#pragma unroll
        for (int g = 0; g < 4; ++g)
#pragma unroll
            for (int r = 0; r < 4; ++r) ls += acc[f][g][r] * acc[f][g][r];
    mma_pass<NCHUNK, false>(zb, Z_LDH * 2, g_BmTH + (size_t)256 * NSd, NSd, bb, acc);
#pragma unroll
    for (int f = 0; f < 4; ++f)
#pragma unroll
        for (int g = 0; g < 4; ++g)
#pragma unroll
            for (int r = 0; r < 4; ++r) ls += acc[f][g][r] * acc[f][g][r];

    float2 bs = block_reduce2(ls, 0.f);
    if (tid == 0) {
        g_jacpart[blockIdx.x] = bs.x;
        __threadfence();
        atomicAdd((unsigned*)(g_ecnt + 254), 1u);
    }

    // ---- CTA 0 finalizes jac_loss ----
    if (blockIdx.x == 0) {
        if (tid == 0) {
            while (g_ecnt[254] < (unsigned)GRID_IT) { }
            __threadfence();
        }
        __syncthreads();
        float s = (tid < GRID_IT) ? __ldcg((const float*)&g_jacpart[tid]) : 0.f;
        float2 tt = block_reduce2(s, 0.f);
        if (tid == 0) out[(size_t)NM * NOUT] = tt.x / ((float)NM * (float)NSd);
    }
}

// ---------------- launcher ----------------
extern "C" void kernel_launch(void* const* d_in, const int* in_sizes, int n_in,
                              void* d_out, int out_size) {
    const float* x   = (const float*)d_in[0];
    const float* A   = (const float*)d_in[1];
    const float* Bm  = (const float*)d_in[2];
    const float* b   = (const float*)d_in[3];
    const float* Wh  = (const float*)d_in[4];
    const float* bh  = (const float*)d_in[5];
    const float* v   = (const float*)d_in[6];
    float* out = (float*)d_out;

    static int configured = 0;
    if (!configured) {
        cudaFuncSetAttribute(k_iter, cudaFuncAttributeMaxDynamicSharedMemorySize, SMEM_DYN);
        configured = 1;
    }

    k_prep<<<(NM * NIN) / 256, 256>>>(x, Bm, A, Wh);
    k_iter<<<GRID_IT, NTH_IT, SMEM_DYN>>>(b, v, bh, out);
}

// round 11
// speedup vs baseline: 1.0347x; 1.0347x over previous
#include <cuda_runtime.h>
#include <cuda_fp16.h>
#include <math.h>
#include <stdint.h>

#define NM    16384
#define NSd   512
#define NIN   64
#define NOUT  64
#define MAXITER   200
#define EPS_STOP  1e-3f

#define GRID_IT   128
#define NTH_IT    512                  // 16 warps
#define KC        64                   // K (halves) per B chunk
#define NCHUNK    8                    // 512 / 64
#define LDH       72                   // staged row pitch (halves)
#define LDB       (LDH * 2)            // 144 B
#define CH_HALF   (256 * LDH)          // 18432 halves per 256-row chunk block
#define CH_BYTES  (CH_HALF * 2)        // 36864 B
#define CHY_HALF  (64 * LDH)           // 4608 halves per 64-row chunk block
#define CHY_BYTES (CHY_HALF * 2)       // 9216 B
#define BSTAGE    CH_BYTES             // smem stage size
#define Z_LDH     520                  // z row pitch halves (1040 B)
#define Z_BYTES   (128 * Z_LDH * 2)    // 133120 B
#define MB_OFF    (Z_BYTES + 2 * BSTAGE)
#define SMEM_DYN  (MB_OFF + 64)        // + mbarrier area
#define XP        400                  // x-composite pitch bytes (200 halves)

// ---------------- device scratch (pre-baked padded operand blocks) ----------------
__device__ float  g_xA[NM * NSd];                       // x@A^T + b (fp32)
__device__ __align__(16) __half g_Bblk [2 * 8 * CH_HALF];   // Bm   [pass][chunk][256x72]
__device__ __align__(16) __half g_BTblk[2 * 8 * CH_HALF];   // Bm^T
__device__ __align__(16) __half g_Ablk [2 * 3 * CH_HALF];   // A-composite [pass][chunk][256x72]
__device__ __align__(16) __half g_Whb  [2 * 8 * CHY_HALF];  // Wh hi/lo [sel][chunk][64x72]
__device__ __align__(16) __half g_xPb  [NM * 200];          // x-composite rows, 200-half pitch
__device__ volatile unsigned g_ecnt[256];
__device__ float g_part[2][2 * GRID_IT];
__device__ float g_jacpart[GRID_IT];

// ---------------- helpers ----------------
__device__ __forceinline__ uint32_t smem_u32(const void* p) {
    uint32_t a;
    asm("{ .reg .u64 t; cvta.to.shared.u64 t, %1; cvt.u32.u64 %0, t; }" : "=r"(a) : "l"(p));
    return a;
}
__device__ __forceinline__ float tanh_ap(float x) {
    float y; asm("tanh.approx.f32 %0, %1;" : "=f"(y) : "f"(x)); return y;
}
__device__ __forceinline__ void ldmatrix_x4(uint32_t r[4], uint32_t addr) {
    asm volatile("ldmatrix.sync.aligned.m8n8.x4.shared.b16 {%0,%1,%2,%3}, [%4];"
        : "=r"(r[0]), "=r"(r[1]), "=r"(r[2]), "=r"(r[3]) : "r"(addr));
}
__device__ __forceinline__ void mma_f16(float c[4], const uint32_t a[4], const uint32_t b[2]) {
    asm volatile(
        "mma.sync.aligned.m16n8k16.row.col.f32.f16.f16.f32 "
        "{%0,%1,%2,%3}, {%4,%5,%6,%7}, {%8,%9}, {%0,%1,%2,%3};"
        : "+f"(c[0]), "+f"(c[1]), "+f"(c[2]), "+f"(c[3])
        : "r"(a[0]), "r"(a[1]), "r"(a[2]), "r"(a[3]), "r"(b[0]), "r"(b[1]));
}
#define MBAR_INIT(a, n) \
    asm volatile("mbarrier.init.shared.b64 [%0], %1;" :: "r"((uint32_t)(a)), "r"((uint32_t)(n)) : "memory")
#define MBAR_EXPECT_TX(a, nb) \
    asm volatile("mbarrier.arrive.expect_tx.shared.b64 _, [%0], %1;" :: "r"((uint32_t)(a)), "r"((uint32_t)(nb)) : "memory")
#define BULK_G2S(dst, src, nb, mbar) \
    asm volatile("cp.async.bulk.shared::cta.global.mbarrier::complete_tx::bytes [%0], [%1], %2, [%3];" \
        :: "r"((uint32_t)(dst)), "l"(src), "r"((uint32_t)(nb)), "r"((uint32_t)(mbar)) : "memory")
#define MBAR_WAIT(a, par) do {                                                             \
    uint32_t _m = (uint32_t)(a); uint32_t _p = (uint32_t)(par); uint32_t _d;               \
    asm volatile("{\n\t.reg .pred p;\n\t"                                                  \
        "mbarrier.try_wait.parity.acquire.cta.shared::cta.b64 p, [%1], %2;\n\t"            \
        "selp.b32 %0, 1, 0, p;\n\t}" : "=r"(_d) : "r"(_m), "r"(_p) : "memory");            \
    if (!_d) {                                                                             \
        asm volatile("{\n\t.reg .pred P1;\n\t"                                             \
            "WL_%=:\n\t"                                                                   \
            "mbarrier.try_wait.parity.acquire.cta.shared::cta.b64 P1, [%0], %1, 0x989680;\n\t" \
            "@P1 bra.uni WD_%=;\n\t"                                                       \
            "bra.uni WL_%=;\n\t"                                                           \
            "WD_%=:\n\t}" :: "r"(_m), "r"(_p) : "memory");                                 \
    }                                                                                      \
} while (0)

// Fused deterministic block reduce of two floats.
__device__ __forceinline__ float2 block_reduce2(float a, float b) {
    __shared__ float2 sr[16];
#pragma unroll
    for (int o = 16; o > 0; o >>= 1) {
        a += __shfl_xor_sync(0xFFFFFFFFu, a, o);
        b += __shfl_xor_sync(0xFFFFFFFFu, b, o);
    }
    const int w = threadIdx.x >> 5, lane = threadIdx.x & 31;
    __syncthreads();
    if (lane == 0) sr[w] = make_float2(a, b);
    __syncthreads();
    float2 t = make_float2(0.f, 0.f);
#pragma unroll
    for (int i = 0; i < 16; ++i) { t.x += sr[i].x; t.y += sr[i].y; }
    return t;
}

// ---------------- fp16 mma pass, A resident in SMEM, B via cp.async.bulk ----------------
// acc[128x256] = Aop(128 x NC*64 @ aBase, pitch aPitchB) @ B(256 x NC*64)^T
// Bblk: contiguous padded chunk blocks of CH_BYTES each.
template<int NC, bool SYNC>
__device__ void mma_pass(uint32_t aBase, int aPitchB,
                         const __half* __restrict__ Bblk,
                         uint32_t bb, uint32_t mb, int& ph0, int& ph1,
                         float acc[4][4][4]) {
    const int tid = threadIdx.x;
    const int w = tid >> 5, lane = tid & 31;
    const int wr = w >> 3, wc = w & 7;

#pragma unroll
    for (int f = 0; f < 4; ++f)
#pragma unroll
        for (int g = 0; g < 4; ++g)
#pragma unroll
            for (int r = 0; r < 4; ++r) acc[f][g][r] = 0.f;

    if (SYNC) __syncthreads();

    if (tid == 0) {
        MBAR_EXPECT_TX(mb, CH_BYTES);
        BULK_G2S(bb, Bblk, CH_BYTES, mb);
    }

    const int rsel = lane & 15;
    const int ksel = (lane >> 4) << 3;
    const uint32_t arow = aBase + (uint32_t)((wr * 64 + rsel) * aPitchB);

    for (int c = 0; c < NC; ++c) {
        if ((c & 1) == 0) { MBAR_WAIT(mb, ph0 & 1); ph0++; }
        else              { MBAR_WAIT(mb + 8, ph1 & 1); ph1++; }
        __syncthreads();   // stage of chunk c-1's sibling is now free for refill

        if (c + 1 < NC && tid == 0) {
            const uint32_t m2 = mb + ((c + 1) & 1) * 8;
            MBAR_EXPECT_TX(m2, CH_BYTES);
            BULK_G2S(bb + ((c + 1) & 1) * BSTAGE, Bblk + (size_t)(c + 1) * CH_HALF,
                     CH_BYTES, m2);
        }

        const uint32_t sB = bb + (uint32_t)((c & 1) * BSTAGE);
#pragma unroll
        for (int ks = 0; ks < 4; ++ks) {
            const uint32_t koff = (uint32_t)((ks * 16 + ksel) * 2);
            const uint32_t akoff = (uint32_t)(c * (KC * 2)) + koff;
            uint32_t a[4][4], bf[2][4];
#pragma unroll
            for (int f = 0; f < 4; ++f)
                ldmatrix_x4(a[f], arow + (uint32_t)(f * 16 * aPitchB) + akoff);
#pragma unroll
            for (int h = 0; h < 2; ++h)
                ldmatrix_x4(bf[h], sB + (uint32_t)((wc * 32 + h * 16 + rsel) * LDB) + koff);
#pragma unroll
            for (int f = 0; f < 4; ++f) {
                { uint32_t b2[2] = {bf[0][0], bf[0][2]}; mma_f16(acc[f][0], a[f], b2); }
                { uint32_t b2[2] = {bf[0][1], bf[0][3]}; mma_f16(acc[f][1], a[f], b2); }
                { uint32_t b2[2] = {bf[1][0], bf[1][2]}; mma_f16(acc[f][2], a[f], b2); }
                { uint32_t b2[2] = {bf[1][1], bf[1][3]}; mma_f16(acc[f][3], a[f], b2); }
            }
        }
    }
}

// ---------------- y pass: acc[128x64] (+)= Z(128x512) @ Wh(64x512)^T ----------------
template<bool ZERO, bool SYNC>
__device__ void mma_pass_y(uint32_t zb, const __half* __restrict__ Bblk,
                           uint32_t bb, uint32_t mb, int& ph0, int& ph1,
                           float acc[4][4]) {
    const int tid = threadIdx.x;
    const int w = tid >> 5, lane = tid & 31;
    const int wm = w >> 1, wn = w & 1;
    if (ZERO) {
#pragma unroll
        for (int g = 0; g < 4; ++g)
#pragma unroll
            for (int r = 0; r < 4; ++r) acc[g][r] = 0.f;
    }
    if (SYNC) __syncthreads();
    if (tid == 0) {
        MBAR_EXPECT_TX(mb, CHY_BYTES);
        BULK_G2S(bb, Bblk, CHY_BYTES, mb);
    }
    const int rsel = lane & 15;
    const int ksel = (lane >> 4) << 3;
    const uint32_t arow = zb + (uint32_t)((wm * 16 + rsel) * (Z_LDH * 2));
    for (int c = 0; c < NCHUNK; ++c) {
        if ((c & 1) == 0) { MBAR_WAIT(mb, ph0 & 1); ph0++; }
        else              { MBAR_WAIT(mb + 8, ph1 & 1); ph1++; }
        __syncthreads();
        if (c + 1 < NCHUNK && tid == 0) {
            const uint32_t m2 = mb + ((c + 1) & 1) * 8;
            MBAR_EXPECT_TX(m2, CHY_BYTES);
            BULK_G2S(bb + ((c + 1) & 1) * BSTAGE, Bblk + (size_t)(c + 1) * CHY_HALF,
                     CHY_BYTES, m2);
        }
        const uint32_t sB = bb + (uint32_t)((c & 1) * BSTAGE);
#pragma unroll
        for (int ks = 0; ks < 4; ++ks) {
            const uint32_t koff = (uint32_t)((ks * 16 + ksel) * 2);
            uint32_t a[4], bf[2][4];
            ldmatrix_x4(a, arow + (uint32_t)(c * (KC * 2)) + koff);
#pragma unroll
            for (int h = 0; h < 2; ++h)
                ldmatrix_x4(bf[h], sB + (uint32_t)((wn * 32 + h * 16 + rsel) * LDB) + koff);
            { uint32_t b2[2] = {bf[0][0], bf[0][2]}; mma_f16(acc[0], a, b2); }
            { uint32_t b2[2] = {bf[0][1], bf[0][3]}; mma_f16(acc[1], a, b2); }
            { uint32_t b2[2] = {bf[1][0], bf[1][2]}; mma_f16(acc[2], a, b2); }
            { uint32_t b2[2] = {bf[1][1], bf[1][3]}; mma_f16(acc[3], a, b2); }
        }
    }
}

// ---------------- k_prep: bake padded operand blocks ----------------
__global__ void k_prep(const float* __restrict__ x,
                       const float* __restrict__ Bm,
                       const float* __restrict__ A,
                       const float* __restrict__ Wh) {
    const int gid = blockIdx.x * 256 + threadIdx.x;
    const int NTOT = gridDim.x * 256;               // 1,048,576

    // Bm and Bm^T blocks: [pass][chunk][256 rows x 72]
    for (int d = gid; d < 2 * 8 * CH_HALF; d += NTOT) {
        const int col = d % LDH;
        const int r = (d / LDH) & 255;
        const int c = (d / (LDH * 256)) & 7;
        const int p = d / (LDH * 256 * 8);
        const int n = p * 256 + r;
        __half hv = __half(0), ht = __half(0);
        if (col < 64) {
            const int k = c * 64 + col;
            hv = __float2half_rn(Bm[n * NSd + k]);
            ht = __float2half_rn(Bm[k * NSd + n]);
        }
        g_Bblk[d] = hv;
        g_BTblk[d] = ht;
    }
    // A-composite blocks: [pass][chunk0..2][256 x 72]; chunks: hi | hi | lo
    for (int d = gid; d < 2 * 3 * CH_HALF; d += NTOT) {
        const int col = d % LDH;
        const int r = (d / LDH) & 255;
        const int c = (d / (LDH * 256)) % 3;
        const int p = d / (LDH * 256 * 3);
        __half hv = __half(0);
        if (col < 64) {
            const float av = A[(p * 256 + r) * NIN + col];
            const __half hi = __float2half_rn(av);
            hv = (c == 2) ? __float2half_rn(av - __half2float(hi)) : hi;
        }
        g_Ablk[d] = hv;
    }
    // Wh hi/lo blocks: [sel][chunk][64 x 72]
    for (int d = gid; d < 2 * 8 * CHY_HALF; d += NTOT) {
        const int col = d % LDH;
        const int r = (d / LDH) & 63;
        const int c = (d / (LDH * 64)) & 7;
        const int s = d / (LDH * 64 * 8);
        __half hv = __half(0);
        if (col < 64) {
            const float wv = Wh[r * NSd + c * 64 + col];
            const __half hi = __float2half_rn(wv);
            hv = s ? __float2half_rn(wv - __half2float(hi)) : hi;
        }
        g_Whb[d] = hv;
    }
    // x-composite rows, 200-half pitch: [hi(64)|lo(64)|hi(64)|pad(8)]
    for (int d = gid; d < NM * 200; d += NTOT) {
        const int col = d % 200;
        const int m = d / 200;
        __half hv = __half(0);
        if (col < 192) {
            const int k = col & 63, s = col >> 6;
            const float xv = x[m * NIN + k];
            const __half hi = __float2half_rn(xv);
            hv = (s == 1) ? __float2half_rn(xv - __half2float(hi)) : hi;
        }
        g_xPb[d] = hv;
    }
    if (gid < 256) g_ecnt[gid] = 0u;
}

// ---------------- persistent solver ----------------
__global__ void __launch_bounds__(NTH_IT, 1) k_iter(const float* __restrict__ bvec,
                                                    const float* __restrict__ v,
                                                    const float* __restrict__ bhv,
                                                    float* __restrict__ out) {
    extern __shared__ __half smh[];
    const uint32_t zb = smem_u32(smh);
    const uint32_t bb = zb + (uint32_t)Z_BYTES;
    const uint32_t mb = zb + (uint32_t)MB_OFF;
    const uint32_t mbx = mb + 16;
    const int tid = threadIdx.x;
    const int w = tid >> 5, lane = tid & 31;
    const int wr = w >> 3, wc = w & 7;
    const int grp = lane >> 2, tg = lane & 3;
    const int m0 = blockIdx.x * 128;
    float acc[4][4][4];
    uint32_t stash[32];
    int ph0 = 0, ph1 = 0;

    if (tid == 0) { MBAR_INIT(mb, 1); MBAR_INIT(mb + 8, 1); MBAR_INIT(mbx, 1); }
    __syncthreads();

    const int mbase = wr * 64 + grp;
    float* xaRow = g_xA + (size_t)(m0 + mbase) * NSd;
    const float* vRow = v + (size_t)(m0 + mbase) * NSd;

    // ---- xA phase: composite x (K=192) -> exact-grade xA; z1 = tanh(xA) ----
    {
        if (tid == 0) {
            MBAR_EXPECT_TX(mbx, 128 * XP);
            BULK_G2S(zb, g_xPb + (size_t)m0 * 200, 128 * XP, mbx);
        }
        MBAR_WAIT(mbx, 0);

        mma_pass<3, true>(zb, XP, g_Ablk, bb, mb, ph0, ph1, acc);
#pragma unroll
        for (int f = 0; f < 4; ++f) {
#pragma unroll
            for (int g = 0; g < 4; ++g) {
                const int n = wc * 32 + g * 8 + tg * 2;
                float2 b2 = *(const float2*)&bvec[n];
#pragma unroll
                for (int hr = 0; hr < 2; ++hr) {
                    const int off = (f * 16 + hr * 8) * NSd + n;
                    const float xx = acc[f][g][hr * 2 + 0] + b2.x;
                    const float xy = acc[f][g][hr * 2 + 1] + b2.y;
                    *(float2*)&xaRow[off] = make_float2(xx, xy);
                    __half2 hh = __halves2half2(__float2half_rn(tanh_ap(xx)),
                                                __float2half_rn(tanh_ap(xy)));
                    stash[(f * 4 + g) * 2 + hr] = *reinterpret_cast<uint32_t*>(&hh);
                }
            }
        }
        mma_pass<3, true>(zb, XP, g_Ablk + (size_t)3 * CH_HALF, bb, mb, ph0, ph1, acc);
        __syncthreads();   // pass-1 GEMM reads of x-tile done -> overwrite with z
#pragma unroll
        for (int f = 0; f < 4; ++f) {
#pragma unroll
            for (int g = 0; g < 4; ++g) {
                const int n = wc * 32 + g * 8 + tg * 2;
                float2 b2 = *(const float2*)&bvec[256 + n];
#pragma unroll
                for (int hr = 0; hr < 2; ++hr) {
                    const int ml = mbase + f * 16 + hr * 8;
                    const int off = (f * 16 + hr * 8) * NSd + 256 + n;
                    const float xx = acc[f][g][hr * 2 + 0] + b2.x;
                    const float xy = acc[f][g][hr * 2 + 1] + b2.y;
                    *(float2*)&xaRow[off] = make_float2(xx, xy);
                    *(__half2*)&smh[ml * Z_LDH + 256 + n] =
                        __halves2half2(__float2half_rn(tanh_ap(xx)),
                                       __float2half_rn(tanh_ap(xy)));
                    *(__half2*)&smh[ml * Z_LDH + n] =
                        *reinterpret_cast<__half2*>(&stash[(f * 4 + g) * 2 + hr]);
                }
            }
        }
    }

    // ---- iterations t = 2..MAXITER with one-iteration-lagged stopping ----
    for (int t = 2; t <= MAXITER; ++t) {
        float lnum = 0.f, lden = 0.f;

        mma_pass<NCHUNK, true>(zb, Z_LDH * 2, g_Bblk, bb, mb, ph0, ph1, acc);
#pragma unroll
        for (int f = 0; f < 4; ++f) {
#pragma unroll
            for (int g = 0; g < 4; ++g) {
                const int n = wc * 32 + g * 8 + tg * 2;
#pragma unroll
                for (int hr = 0; hr < 2; ++hr) {
                    const int ml = mbase + f * 16 + hr * 8;
                    float2 xa = *(const float2*)&xaRow[(f * 16 + hr * 8) * NSd + n];
                    __half hx = __float2half_rn(tanh_ap(xa.x + acc[f][g][hr * 2 + 0]));
                    __half hy = __float2half_rn(tanh_ap(xa.y + acc[f][g][hr * 2 + 1]));
                    const float zx = __half2float(hx), zy = __half2float(hy);
                    __half2 zp = *(__half2*)&smh[ml * Z_LDH + n];
                    const float dx = zx - __low2float(zp);
                    const float dy = zy - __high2float(zp);
                    lnum += dx * dx + dy * dy;
                    lden += zx * zx + zy * zy;
                    __half2 hh = __halves2half2(hx, hy);
                    stash[(f * 4 + g) * 2 + hr] = *reinterpret_cast<uint32_t*>(&hh);
                }
            }
        }
        mma_pass<NCHUNK, false>(zb, Z_LDH * 2, g_Bblk + (size_t)8 * CH_HALF,
                                bb, mb, ph0, ph1, acc);
        __syncthreads();   // GEMM reads of z done -> overwrite
#pragma unroll
        for (int f = 0; f < 4; ++f) {
#pragma unroll
            for (int g = 0; g < 4; ++g) {
                const int n = wc * 32 + g * 8 + tg * 2;
#pragma unroll
                for (int hr = 0; hr < 2; ++hr) {
                    const int ml = mbase + f * 16 + hr * 8;
                    const int n2 = 256 + n;
                    float2 xa = *(const float2*)&xaRow[(f * 16 + hr * 8) * NSd + n2];
                    __half hx = __float2half_rn(tanh_ap(xa.x + acc[f][g][hr * 2 + 0]));
                    __half hy = __float2half_rn(tanh_ap(xa.y + acc[f][g][hr * 2 + 1]));
                    const float zx = __half2float(hx), zy = __half2float(hy);
                    __half2 zp = *(__half2*)&smh[ml * Z_LDH + n2];
                    const float dx = zx - __low2float(zp);
                    const float dy = zy - __high2float(zp);
                    lnum += dx * dx + dy * dy;
                    lden += zx * zx + zy * zy;
                    *(__half2*)&smh[ml * Z_LDH + n2] = __halves2half2(hx, hy);
                    *(__half2*)&smh[ml * Z_LDH + n] =
                        *reinterpret_cast<__half2*>(&stash[(f * 4 + g) * 2 + hr]);
                }
            }
        }

        float2 bpart = block_reduce2(lnum, lden);
        if (tid == 0) {
            g_part[t & 1][2 * blockIdx.x]     = bpart.x;
            g_part[t & 1][2 * blockIdx.x + 1] = bpart.y;
            __threadfence();
            if (t > 2) {
                while (g_ecnt[t - 1] < (unsigned)GRID_IT) { }
                __threadfence();
            }
        }
        __syncthreads();

        bool stop = false;
        if (t > 2) {
            float pn = 0.f, pd = 0.f;
            if (tid < GRID_IT) {
                float2 pp = __ldcg((const float2*)&g_part[(t - 1) & 1][2 * tid]);
                pn = pp.x; pd = pp.y;
            }
            float2 tot = block_reduce2(pn, pd);
            const float res = sqrtf(tot.x) / (sqrtf(tot.y) + 1e-8f);
            stop = (res <= EPS_STOP);
        }
        __syncthreads();
        if (tid == 0) atomicAdd((unsigned*)(g_ecnt + t), 1u);
        if (stop) break;
    }

    // ---- y = z* @ Wh^T + bh (hi/lo split), written directly to out ----
    {
        float yacc[4][4];
        mma_pass_y<true,  true >(zb, g_Whb, bb, mb, ph0, ph1, yacc);
        mma_pass_y<false, false>(zb, g_Whb + (size_t)8 * CHY_HALF, bb, mb, ph0, ph1, yacc);
        const int wm = w >> 1, wn = w & 1;
#pragma unroll
        for (int g = 0; g < 4; ++g) {
            const int col = wn * 32 + g * 8 + tg * 2;
            float2 b2 = *(const float2*)&bhv[col];
#pragma unroll
            for (int hr = 0; hr < 2; ++hr) {
                const int m = m0 + wm * 16 + grp + hr * 8;
                *(float2*)&out[(size_t)m * NOUT + col] =
                    make_float2(yacc[g][hr * 2] + b2.x, yacc[g][hr * 2 + 1] + b2.y);
            }
        }
    }

    // ---- g-phase: g = v * (1 - tanh(xA + z* @ Bm^T)^2); overwrite z with g ----
    mma_pass<NCHUNK, false>(zb, Z_LDH * 2, g_Bblk, bb, mb, ph0, ph1, acc);
#pragma unroll
    for (int f = 0; f < 4; ++f) {
#pragma unroll
        for (int g = 0; g < 4; ++g) {
            const int n = wc * 32 + g * 8 + tg * 2;
#pragma unroll
            for (int hr = 0; hr < 2; ++hr) {
                const int off = (f * 16 + hr * 8) * NSd + n;
                float2 xa = *(const float2*)&xaRow[off];
                float2 vv = *(const float2*)&vRow[off];
                float th;
                th = tanh_ap(xa.x + acc[f][g][hr * 2 + 0]);
                __half gx = __float2half_rn(vv.x * (1.f - th * th));
                th = tanh_ap(xa.y + acc[f][g][hr * 2 + 1]);
                __half gy = __float2half_rn(vv.y * (1.f - th * th));
                __half2 hh = __halves2half2(gx, gy);
                stash[(f * 4 + g) * 2 + hr] = *reinterpret_cast<uint32_t*>(&hh);
            }
        }
    }
    mma_pass<NCHUNK, false>(zb, Z_LDH * 2, g_Bblk + (size_t)8 * CH_HALF,
                            bb, mb, ph0, ph1, acc);
    __syncthreads();
#pragma unroll
    for (int f = 0; f < 4; ++f) {
#pragma unroll
        for (int g = 0; g < 4; ++g) {
            const int n = wc * 32 + g * 8 + tg * 2;
#pragma unroll
            for (int hr = 0; hr < 2; ++hr) {
                const int ml = mbase + f * 16 + hr * 8;
                const int n2 = 256 + n;
                const int off = (f * 16 + hr * 8) * NSd + n2;
                float2 xa = *(const float2*)&xaRow[off];
                float2 vv = *(const float2*)&vRow[off];
                float th;
                th = tanh_ap(xa.x + acc[f][g][hr * 2 + 0]);
                __half gx = __float2half_rn(vv.x * (1.f - th * th));
                th = tanh_ap(xa.y + acc[f][g][hr * 2 + 1]);
                __half gy = __float2half_rn(vv.y * (1.f - th * th));
                *(__half2*)&smh[ml * Z_LDH + n2] = __halves2half2(gx, gy);
                *(__half2*)&smh[ml * Z_LDH + n] =
                    *reinterpret_cast<__half2*>(&stash[(f * 4 + g) * 2 + hr]);
            }
        }
    }

    // ---- vjp: vJ = g @ Bm ; sum of squares ----
    float ls = 0.f;
    mma_pass<NCHUNK, true>(zb, Z_LDH * 2, g_BTblk, bb, mb, ph0, ph1, acc);
#pragma unroll
    for (int f = 0; f < 4; ++f)
#pragma unroll
        for (int g = 0; g < 4; ++g)
#pragma unroll
            for (int r = 0; r < 4; ++r) ls += acc[f][g][r] * acc[f][g][r];
    mma_pass<NCHUNK, false>(zb, Z_LDH * 2, g_BTblk + (size_t)8 * CH_HALF,
                            bb, mb, ph0, ph1, acc);
#pragma unroll
    for (int f = 0; f < 4; ++f)
#pragma unroll
        for (int g = 0; g < 4; ++g)
#pragma unroll
            for (int r = 0; r < 4; ++r) ls += acc[f][g][r] * acc[f][g][r];

    float2 bs = block_reduce2(ls, 0.f);
    if (tid == 0) {
        g_jacpart[blockIdx.x] = bs.x;
        __threadfence();
        atomicAdd((unsigned*)(g_ecnt + 254), 1u);
    }

    // ---- CTA 0 finalizes jac_loss ----
    if (blockIdx.x == 0) {
        if (tid == 0) {
            while (g_ecnt[254] < (unsigned)GRID_IT) { }
            __threadfence();
        }
        __syncthreads();
        float s = (tid < GRID_IT) ? __ldcg((const float*)&g_jacpart[tid]) : 0.f;
        float2 tt = block_reduce2(s, 0.f);
        if (tid == 0) out[(size_t)NM * NOUT] = tt.x / ((float)NM * (float)NSd);
    }
}

// ---------------- launcher ----------------
extern "C" void kernel_launch(void* const* d_in, const int* in_sizes, int n_in,
                              void* d_out, int out_size) {
    const float* x   = (const float*)d_in[0];
    const float* A   = (const float*)d_in[1];
    const float* Bm  = (const float*)d_in[2];
    const float* b   = (const float*)d_in[3];
    const float* Wh  = (const float*)d_in[4];
    const float* bh  = (const float*)d_in[5];
    const float* v   = (const float*)d_in[6];
    float* out = (float*)d_out;

    static int configured = 0;
    if (!configured) {
        cudaFuncSetAttribute(k_iter, cudaFuncAttributeMaxDynamicSharedMemorySize, SMEM_DYN);
        configured = 1;
    }

    k_prep<<<4096, 256>>>(x, Bm, A, Wh);
    k_iter<<<GRID_IT, NTH_IT, SMEM_DYN>>>(b, v, bh, out);
}

// round 12
// speedup vs baseline: 1.0546x; 1.0192x over previous
#include <cuda_runtime.h>
#include <cuda_fp16.h>
#include <math.h>
#include <stdint.h>

#define NM    16384
#define NSd   512
#define NIN   64
#define NOUT  64
#define MAXITER   200
#define EPS_STOP  1e-3f

#define GRID_IT   128
#define NTH_IT    512                  // 16 warps
#define KC        64                   // K (halves) per B chunk
#define NCHUNK    8                    // 512 / 64
#define LDH       72                   // staged row pitch (halves)
#define LDB       (LDH * 2)            // 144 B
#define CH_HALF   (256 * LDH)          // 18432 halves per 256-row chunk block
#define CH_BYTES  (CH_HALF * 2)        // 36864 B
#define CHY_HALF  (64 * LDH)           // 4608 halves per 64-row chunk block
#define CHY_BYTES (CHY_HALF * 2)       // 9216 B
#define BSTAGE    CH_BYTES             // smem stage size
#define Z_LDH     520                  // z row pitch halves (1040 B)
#define Z_BYTES   (128 * Z_LDH * 2)    // 133120 B
#define MB_OFF    (Z_BYTES + 2 * BSTAGE)
#define SMEM_DYN  (MB_OFF + 64)        // + mbarrier area
#define XP        400                  // x-composite pitch bytes (200 halves)

// ---------------- device scratch (pre-baked padded operand blocks) ----------------
__device__ float  g_xA[NM * NSd];                       // x@A^T + b (fp32)
__device__ __align__(16) __half g_Bblk [2 * 8 * CH_HALF];   // Bm   [pass][chunk][256x72]
__device__ __align__(16) __half g_BTblk[2 * 8 * CH_HALF];   // Bm^T
__device__ __align__(16) __half g_Ablk [2 * 3 * CH_HALF];   // A-composite [pass][chunk][256x72]
__device__ __align__(16) __half g_Whb  [2 * 8 * CHY_HALF];  // Wh hi/lo [sel][chunk][64x72]
__device__ __align__(16) __half g_xPb  [NM * 200];          // x-composite rows, 200-half pitch
__device__ volatile unsigned g_ecnt[256];
__device__ float g_part[2][2 * GRID_IT];
__device__ float g_jacpart[GRID_IT];

// ---------------- helpers ----------------
__device__ __forceinline__ uint32_t smem_u32(const void* p) {
    uint32_t a;
    asm("{ .reg .u64 t; cvta.to.shared.u64 t, %1; cvt.u32.u64 %0, t; }" : "=r"(a) : "l"(p));
    return a;
}
__device__ __forceinline__ float tanh_ap(float x) {
    float y; asm("tanh.approx.f32 %0, %1;" : "=f"(y) : "f"(x)); return y;
}
__device__ __forceinline__ void ldmatrix_x4(uint32_t r[4], uint32_t addr) {
    asm volatile("ldmatrix.sync.aligned.m8n8.x4.shared.b16 {%0,%1,%2,%3}, [%4];"
        : "=r"(r[0]), "=r"(r[1]), "=r"(r[2]), "=r"(r[3]) : "r"(addr));
}
__device__ __forceinline__ void mma_f16(float c[4], const uint32_t a[4], const uint32_t b[2]) {
    asm volatile(
        "mma.sync.aligned.m16n8k16.row.col.f32.f16.f16.f32 "
        "{%0,%1,%2,%3}, {%4,%5,%6,%7}, {%8,%9}, {%0,%1,%2,%3};"
        : "+f"(c[0]), "+f"(c[1]), "+f"(c[2]), "+f"(c[3])
        : "r"(a[0]), "r"(a[1]), "r"(a[2]), "r"(a[3]), "r"(b[0]), "r"(b[1]));
}
#define MBAR_INIT(a, n) \
    asm volatile("mbarrier.init.shared.b64 [%0], %1;" :: "r"((uint32_t)(a)), "r"((uint32_t)(n)) : "memory")
#define MBAR_EXPECT_TX(a, nb) \
    asm volatile("mbarrier.arrive.expect_tx.shared.b64 _, [%0], %1;" :: "r"((uint32_t)(a)), "r"((uint32_t)(nb)) : "memory")
#define BULK_G2S(dst, src, nb, mbar) \
    asm volatile("cp.async.bulk.shared::cta.global.mbarrier::complete_tx::bytes [%0], [%1], %2, [%3];" \
        :: "r"((uint32_t)(dst)), "l"(src), "r"((uint32_t)(nb)), "r"((uint32_t)(mbar)) : "memory")
#define MBAR_WAIT(a, par) do {                                                             \
    uint32_t _m = (uint32_t)(a); uint32_t _p = (uint32_t)(par); uint32_t _d;               \
    asm volatile("{\n\t.reg .pred p;\n\t"                                                  \
        "mbarrier.try_wait.parity.acquire.cta.shared::cta.b64 p, [%1], %2;\n\t"            \
        "selp.b32 %0, 1, 0, p;\n\t}" : "=r"(_d) : "r"(_m), "r"(_p) : "memory");            \
    if (!_d) {                                                                             \
        asm volatile("{\n\t.reg .pred P1;\n\t"                                             \
            "WL_%=:\n\t"                                                                   \
            "mbarrier.try_wait.parity.acquire.cta.shared::cta.b64 P1, [%0], %1, 0x989680;\n\t" \
            "@P1 bra.uni WD_%=;\n\t"                                                       \
            "bra.uni WL_%=;\n\t"                                                           \
            "WD_%=:\n\t}" :: "r"(_m), "r"(_p) : "memory");                                 \
    }                                                                                      \
} while (0)

// Fused deterministic block reduce of two floats.
__device__ __forceinline__ float2 block_reduce2(float a, float b) {
    __shared__ float2 sr[16];
#pragma unroll
    for (int o = 16; o > 0; o >>= 1) {
        a += __shfl_xor_sync(0xFFFFFFFFu, a, o);
        b += __shfl_xor_sync(0xFFFFFFFFu, b, o);
    }
    const int w = threadIdx.x >> 5, lane = threadIdx.x & 31;
    __syncthreads();
    if (lane == 0) sr[w] = make_float2(a, b);
    __syncthreads();
    float2 t = make_float2(0.f, 0.f);
#pragma unroll
    for (int i = 0; i < 16; ++i) { t.x += sr[i].x; t.y += sr[i].y; }
    return t;
}

// ---------------- fp16 mma pass, A resident in SMEM, B via cp.async.bulk ----------------
// acc[128x256] = Aop(128 x NC*64 @ aBase, pitch aPitchB) @ B(256 x NC*64)^T
// skipFirst: chunk 0 already in flight (preloaded by the previous pass).
// preNext/preBytes: if non-null, issue next pass's chunk 0 into stage NC&1 at the
// top of the last chunk (stage provably free: its last use was chunk NC-2).
template<int NC, bool SYNC>
__device__ void mma_pass(uint32_t aBase, int aPitchB,
                         const __half* __restrict__ Bblk,
                         const __half* __restrict__ preNext, uint32_t preBytes,
                         bool skipFirst,
                         uint32_t bb, uint32_t mb, int& ph0, int& ph1,
                         float acc[4][4][4]) {
    const int tid = threadIdx.x;
    const int w = tid >> 5, lane = tid & 31;
    const int wr = w >> 3, wc = w & 7;

#pragma unroll
    for (int f = 0; f < 4; ++f)
#pragma unroll
        for (int g = 0; g < 4; ++g)
#pragma unroll
            for (int r = 0; r < 4; ++r) acc[f][g][r] = 0.f;

    if (SYNC) __syncthreads();

    if (!skipFirst && tid == 0) {
        MBAR_EXPECT_TX(mb, CH_BYTES);
        BULK_G2S(bb, Bblk, CH_BYTES, mb);
    }

    const int rsel = lane & 15;
    const int ksel = (lane >> 4) << 3;
    const uint32_t arow = aBase + (uint32_t)((wr * 64 + rsel) * aPitchB);

    for (int c = 0; c < NC; ++c) {
        if ((c & 1) == 0) { MBAR_WAIT(mb, ph0 & 1); ph0++; }
        else              { MBAR_WAIT(mb + 8, ph1 & 1); ph1++; }
        __syncthreads();   // stage of chunk c-1's sibling is now free for refill

        if (tid == 0) {
            if (c + 1 < NC) {
                const uint32_t m2 = mb + ((c + 1) & 1) * 8;
                MBAR_EXPECT_TX(m2, CH_BYTES);
                BULK_G2S(bb + ((c + 1) & 1) * BSTAGE, Bblk + (size_t)(c + 1) * CH_HALF,
                         CH_BYTES, m2);
            } else if (preNext) {
                const uint32_t m2 = mb + ((c + 1) & 1) * 8;
                MBAR_EXPECT_TX(m2, preBytes);
                BULK_G2S(bb + ((c + 1) & 1) * BSTAGE, preNext, preBytes, m2);
            }
        }

        const uint32_t sB = bb + (uint32_t)((c & 1) * BSTAGE);
#pragma unroll
        for (int ks = 0; ks < 4; ++ks) {
            const uint32_t koff = (uint32_t)((ks * 16 + ksel) * 2);
            const uint32_t akoff = (uint32_t)(c * (KC * 2)) + koff;
            uint32_t a[4][4], bf[2][4];
#pragma unroll
            for (int f = 0; f < 4; ++f)
                ldmatrix_x4(a[f], arow + (uint32_t)(f * 16 * aPitchB) + akoff);
#pragma unroll
            for (int h = 0; h < 2; ++h)
                ldmatrix_x4(bf[h], sB + (uint32_t)((wc * 32 + h * 16 + rsel) * LDB) + koff);
#pragma unroll
            for (int f = 0; f < 4; ++f) {
                { uint32_t b2[2] = {bf[0][0], bf[0][2]}; mma_f16(acc[f][0], a[f], b2); }
                { uint32_t b2[2] = {bf[0][1], bf[0][3]}; mma_f16(acc[f][1], a[f], b2); }
                { uint32_t b2[2] = {bf[1][0], bf[1][2]}; mma_f16(acc[f][2], a[f], b2); }
                { uint32_t b2[2] = {bf[1][1], bf[1][3]}; mma_f16(acc[f][3], a[f], b2); }
            }
        }
    }
}

// ---------------- y pass: acc[128x64] (+)= Z(128x512) @ Wh(64x512)^T ----------------
template<bool ZERO>
__device__ void mma_pass_y(uint32_t zb, const __half* __restrict__ Bblk,
                           const __half* __restrict__ preNext, uint32_t preBytes,
                           bool skipFirst,
                           uint32_t bb, uint32_t mb, int& ph0, int& ph1,
                           float acc[4][4]) {
    const int tid = threadIdx.x;
    const int w = tid >> 5, lane = tid & 31;
    const int wm = w >> 1, wn = w & 1;
    if (ZERO) {
#pragma unroll
        for (int g = 0; g < 4; ++g)
#pragma unroll
            for (int r = 0; r < 4; ++r) acc[g][r] = 0.f;
    }
    if (!skipFirst && tid == 0) {
        MBAR_EXPECT_TX(mb, CHY_BYTES);
        BULK_G2S(bb, Bblk, CHY_BYTES, mb);
    }
    const int rsel = lane & 15;
    const int ksel = (lane >> 4) << 3;
    const uint32_t arow = zb + (uint32_t)((wm * 16 + rsel) * (Z_LDH * 2));
    for (int c = 0; c < NCHUNK; ++c) {
        if ((c & 1) == 0) { MBAR_WAIT(mb, ph0 & 1); ph0++; }
        else              { MBAR_WAIT(mb + 8, ph1 & 1); ph1++; }
        __syncthreads();
        if (tid == 0) {
            if (c + 1 < NCHUNK) {
                const uint32_t m2 = mb + ((c + 1) & 1) * 8;
                MBAR_EXPECT_TX(m2, CHY_BYTES);
                BULK_G2S(bb + ((c + 1) & 1) * BSTAGE, Bblk + (size_t)(c + 1) * CHY_HALF,
                         CHY_BYTES, m2);
            } else if (preNext) {
                const uint32_t m2 = mb + ((c + 1) & 1) * 8;
                MBAR_EXPECT_TX(m2, preBytes);
                BULK_G2S(bb + ((c + 1) & 1) * BSTAGE, preNext, preBytes, m2);
            }
        }
        const uint32_t sB = bb + (uint32_t)((c & 1) * BSTAGE);
#pragma unroll
        for (int ks = 0; ks < 4; ++ks) {
            const uint32_t koff = (uint32_t)((ks * 16 + ksel) * 2);
            uint32_t a[4], bf[2][4];
            ldmatrix_x4(a, arow + (uint32_t)(c * (KC * 2)) + koff);
#pragma unroll
            for (int h = 0; h < 2; ++h)
                ldmatrix_x4(bf[h], sB + (uint32_t)((wn * 32 + h * 16 + rsel) * LDB) + koff);
            { uint32_t b2[2] = {bf[0][0], bf[0][2]}; mma_f16(acc[0], a, b2); }
            { uint32_t b2[2] = {bf[0][1], bf[0][3]}; mma_f16(acc[1], a, b2); }
            { uint32_t b2[2] = {bf[1][0], bf[1][2]}; mma_f16(acc[2], a, b2); }
            { uint32_t b2[2] = {bf[1][1], bf[1][3]}; mma_f16(acc[3], a, b2); }
        }
    }
}

// ---------------- k_prep: bake padded operand blocks ----------------
__global__ void k_prep(const float* __restrict__ x,
                       const float* __restrict__ Bm,
                       const float* __restrict__ A,
                       const float* __restrict__ Wh) {
    const int gid = blockIdx.x * 256 + threadIdx.x;
    const int NTOT = gridDim.x * 256;

    for (int d = gid; d < 2 * 8 * CH_HALF; d += NTOT) {
        const int col = d % LDH;
        const int r = (d / LDH) & 255;
        const int c = (d / (LDH * 256)) & 7;
        const int p = d / (LDH * 256 * 8);
        const int n = p * 256 + r;
        __half hv = __half(0), ht = __half(0);
        if (col < 64) {
            const int k = c * 64 + col;
            hv = __float2half_rn(Bm[n * NSd + k]);
            ht = __float2half_rn(Bm[k * NSd + n]);
        }
        g_Bblk[d] = hv;
        g_BTblk[d] = ht;
    }
    for (int d = gid; d < 2 * 3 * CH_HALF; d += NTOT) {
        const int col = d % LDH;
        const int r = (d / LDH) & 255;
        const int c = (d / (LDH * 256)) % 3;
        const int p = d / (LDH * 256 * 3);
        __half hv = __half(0);
        if (col < 64) {
            const float av = A[(p * 256 + r) * NIN + col];
            const __half hi = __float2half_rn(av);
            hv = (c == 2) ? __float2half_rn(av - __half2float(hi)) : hi;
        }
        g_Ablk[d] = hv;
    }
    for (int d = gid; d < 2 * 8 * CHY_HALF; d += NTOT) {
        const int col = d % LDH;
        const int r = (d / LDH) & 63;
        const int c = (d / (LDH * 64)) & 7;
        const int s = d / (LDH * 64 * 8);
        __half hv = __half(0);
        if (col < 64) {
            const float wv = Wh[r * NSd + c * 64 + col];
            const __half hi = __float2half_rn(wv);
            hv = s ? __float2half_rn(wv - __half2float(hi)) : hi;
        }
        g_Whb[d] = hv;
    }
    for (int d = gid; d < NM * 200; d += NTOT) {
        const int col = d % 200;
        const int m = d / 200;
        __half hv = __half(0);
        if (col < 192) {
            const int k = col & 63, s = col >> 6;
            const float xv = x[m * NIN + k];
            const __half hi = __float2half_rn(xv);
            hv = (s == 1) ? __float2half_rn(xv - __half2float(hi)) : hi;
        }
        g_xPb[d] = hv;
    }
    if (gid < 256) g_ecnt[gid] = 0u;
}

// ---------------- persistent solver ----------------
__global__ void __launch_bounds__(NTH_IT, 1) k_iter(const float* __restrict__ bvec,
                                                    const float* __restrict__ v,
                                                    const float* __restrict__ bhv,
                                                    float* __restrict__ out) {
    extern __shared__ __half smh[];
    const uint32_t zb = smem_u32(smh);
    const uint32_t bb = zb + (uint32_t)Z_BYTES;
    const uint32_t mb = zb + (uint32_t)MB_OFF;
    const uint32_t mbx = mb + 16;
    const int tid = threadIdx.x;
    const int w = tid >> 5, lane = tid & 31;
    const int wr = w >> 3, wc = w & 7;
    const int grp = lane >> 2, tg = lane & 3;
    const int m0 = blockIdx.x * 128;
    float acc[4][4][4];
    uint32_t stash[32];
    int ph0 = 0, ph1 = 0;

    if (tid == 0) { MBAR_INIT(mb, 1); MBAR_INIT(mb + 8, 1); MBAR_INIT(mbx, 1); }
    __syncthreads();

    const int mbase = wr * 64 + grp;
    float* xaRow = g_xA + (size_t)(m0 + mbase) * NSd;
    const float* vRow = v + (size_t)(m0 + mbase) * NSd;

    // ---- xA phase: composite x (K=192) -> exact-grade xA; z1 = tanh(xA) ----
    {
        if (tid == 0) {
            MBAR_EXPECT_TX(mbx, 128 * XP);
            BULK_G2S(zb, g_xPb + (size_t)m0 * 200, 128 * XP, mbx);
        }
        MBAR_WAIT(mbx, 0);

        mma_pass<3, true>(zb, XP, g_Ablk, (const __half*)0, 0, false,
                          bb, mb, ph0, ph1, acc);
#pragma unroll
        for (int f = 0; f < 4; ++f) {
#pragma unroll
            for (int g = 0; g < 4; ++g) {
                const int n = wc * 32 + g * 8 + tg * 2;
                float2 b2 = *(const float2*)&bvec[n];
#pragma unroll
                for (int hr = 0; hr < 2; ++hr) {
                    const int off = (f * 16 + hr * 8) * NSd + n;
                    const float xx = acc[f][g][hr * 2 + 0] + b2.x;
                    const float xy = acc[f][g][hr * 2 + 1] + b2.y;
                    *(float2*)&xaRow[off] = make_float2(xx, xy);
                    __half2 hh = __halves2half2(__float2half_rn(tanh_ap(xx)),
                                                __float2half_rn(tanh_ap(xy)));
                    stash[(f * 4 + g) * 2 + hr] = *reinterpret_cast<uint32_t*>(&hh);
                }
            }
        }
        mma_pass<3, true>(zb, XP, g_Ablk + (size_t)3 * CH_HALF, (const __half*)0, 0, false,
                          bb, mb, ph0, ph1, acc);
        __syncthreads();   // pass-1 GEMM reads of x-tile done -> overwrite with z
#pragma unroll
        for (int f = 0; f < 4; ++f) {
#pragma unroll
            for (int g = 0; g < 4; ++g) {
                const int n = wc * 32 + g * 8 + tg * 2;
                float2 b2 = *(const float2*)&bvec[256 + n];
#pragma unroll
                for (int hr = 0; hr < 2; ++hr) {
                    const int ml = mbase + f * 16 + hr * 8;
                    const int off = (f * 16 + hr * 8) * NSd + 256 + n;
                    const float xx = acc[f][g][hr * 2 + 0] + b2.x;
                    const float xy = acc[f][g][hr * 2 + 1] + b2.y;
                    *(float2*)&xaRow[off] = make_float2(xx, xy);
                    *(__half2*)&smh[ml * Z_LDH + 256 + n] =
                        __halves2half2(__float2half_rn(tanh_ap(xx)),
                                       __float2half_rn(tanh_ap(xy)));
                    *(__half2*)&smh[ml * Z_LDH + n] =
                        *reinterpret_cast<__half2*>(&stash[(f * 4 + g) * 2 + hr]);
                }
            }
        }
    }

    // ---- iterations t = 2..MAXITER; prefetch-chained passes, lagged stop ----
    for (int t = 2; t <= MAXITER; ++t) {
        float lnum = 0.f, lden = 0.f;

        // pass0: preloads pass1's chunk 0. First iteration loads its own chunk 0.
        mma_pass<NCHUNK, true>(zb, Z_LDH * 2, g_Bblk,
                               g_Bblk + (size_t)8 * CH_HALF, CH_BYTES, t != 2,
                               bb, mb, ph0, ph1, acc);
#pragma unroll
        for (int f = 0; f < 4; ++f) {
#pragma unroll
            for (int g = 0; g < 4; ++g) {
                const int n = wc * 32 + g * 8 + tg * 2;
#pragma unroll
                for (int hr = 0; hr < 2; ++hr) {
                    const int ml = mbase + f * 16 + hr * 8;
                    float2 xa = *(const float2*)&xaRow[(f * 16 + hr * 8) * NSd + n];
                    __half hx = __float2half_rn(tanh_ap(xa.x + acc[f][g][hr * 2 + 0]));
                    __half hy = __float2half_rn(tanh_ap(xa.y + acc[f][g][hr * 2 + 1]));
                    const float zx = __half2float(hx), zy = __half2float(hy);
                    __half2 zp = *(__half2*)&smh[ml * Z_LDH + n];
                    const float dx = zx - __low2float(zp);
                    const float dy = zy - __high2float(zp);
                    lnum += dx * dx + dy * dy;
                    lden += zx * zx + zy * zy;
                    __half2 hh = __halves2half2(hx, hy);
                    stash[(f * 4 + g) * 2 + hr] = *reinterpret_cast<uint32_t*>(&hh);
                }
            }
        }
        // pass1: preloads g_Bblk chunk 0 — correct whether we iterate again OR
        // fall through to the g-phase; only the y-pass transition discards it.
        mma_pass<NCHUNK, false>(zb, Z_LDH * 2, g_Bblk + (size_t)8 * CH_HALF,
                                g_Bblk, CH_BYTES, true,
                                bb, mb, ph0, ph1, acc);
        __syncthreads();   // GEMM reads of z done -> overwrite
#pragma unroll
        for (int f = 0; f < 4; ++f) {
#pragma unroll
            for (int g = 0; g < 4; ++g) {
                const int n = wc * 32 + g * 8 + tg * 2;
#pragma unroll
                for (int hr = 0; hr < 2; ++hr) {
                    const int ml = mbase + f * 16 + hr * 8;
                    const int n2 = 256 + n;
                    float2 xa = *(const float2*)&xaRow[(f * 16 + hr * 8) * NSd + n2];
                    __half hx = __float2half_rn(tanh_ap(xa.x + acc[f][g][hr * 2 + 0]));
                    __half hy = __float2half_rn(tanh_ap(xa.y + acc[f][g][hr * 2 + 1]));
                    const float zx = __half2float(hx), zy = __half2float(hy);
                    __half2 zp = *(__half2*)&smh[ml * Z_LDH + n2];
                    const float dx = zx - __low2float(zp);
                    const float dy = zy - __high2float(zp);
                    lnum += dx * dx + dy * dy;
                    lden += zx * zx + zy * zy;
                    *(__half2*)&smh[ml * Z_LDH + n2] = __halves2half2(hx, hy);
                    *(__half2*)&smh[ml * Z_LDH + n] =
                        *reinterpret_cast<__half2*>(&stash[(f * 4 + g) * 2 + hr]);
                }
            }
        }

        float2 bpart = block_reduce2(lnum, lden);
        if (tid == 0) {
            g_part[t & 1][2 * blockIdx.x]     = bpart.x;
            g_part[t & 1][2 * blockIdx.x + 1] = bpart.y;
            __threadfence();
            if (t > 2) {
                while (g_ecnt[t - 1] < (unsigned)GRID_IT) { }
                __threadfence();
            }
        }
        __syncthreads();

        bool stop = false;
        if (t > 2) {
            float pn = 0.f, pd = 0.f;
            if (tid < GRID_IT) {
                float2 pp = __ldcg((const float2*)&g_part[(t - 1) & 1][2 * tid]);
                pn = pp.x; pd = pp.y;
            }
            float2 tot = block_reduce2(pn, pd);
            const float res = sqrtf(tot.x) / (sqrtf(tot.y) + 1e-8f);
            stop = (res <= EPS_STOP);
        }
        __syncthreads();
        if (tid == 0) atomicAdd((unsigned*)(g_ecnt + t), 1u);
        if (stop) break;
    }

    // Discard the speculative g_Bblk chunk-0 preload (stage 0): consume its arrival.
    MBAR_WAIT(mb, ph0 & 1); ph0++;

    // ---- y = z* @ Wh^T + bh (hi/lo split), written directly to out ----
    {
        float yacc[4][4];
        mma_pass_y<true >(zb, g_Whb, g_Whb + (size_t)8 * CHY_HALF, CHY_BYTES, false,
                          bb, mb, ph0, ph1, yacc);
        mma_pass_y<false>(zb, g_Whb + (size_t)8 * CHY_HALF, g_Bblk, CH_BYTES, true,
                          bb, mb, ph0, ph1, yacc);
        const int wm = w >> 1, wn = w & 1;
#pragma unroll
        for (int g = 0; g < 4; ++g) {
            const int col = wn * 32 + g * 8 + tg * 2;
            float2 b2 = *(const float2*)&bhv[col];
#pragma unroll
            for (int hr = 0; hr < 2; ++hr) {
                const int m = m0 + wm * 16 + grp + hr * 8;
                *(float2*)&out[(size_t)m * NOUT + col] =
                    make_float2(yacc[g][hr * 2] + b2.x, yacc[g][hr * 2 + 1] + b2.y);
            }
        }
    }

    // ---- g-phase: g = v * (1 - tanh(xA + z* @ Bm^T)^2); overwrite z with g ----
    mma_pass<NCHUNK, false>(zb, Z_LDH * 2, g_Bblk,
                            g_Bblk + (size_t)8 * CH_HALF, CH_BYTES, true,
                            bb, mb, ph0, ph1, acc);
#pragma unroll
    for (int f = 0; f < 4; ++f) {
#pragma unroll
        for (int g = 0; g < 4; ++g) {
            const int n = wc * 32 + g * 8 + tg * 2;
#pragma unroll
            for (int hr = 0; hr < 2; ++hr) {
                const int off = (f * 16 + hr * 8) * NSd + n;
                float2 xa = *(const float2*)&xaRow[off];
                float2 vv = *(const float2*)&vRow[off];
                float th;
                th = tanh_ap(xa.x + acc[f][g][hr * 2 + 0]);
                __half gx = __float2half_rn(vv.x * (1.f - th * th));
                th = tanh_ap(xa.y + acc[f][g][hr * 2 + 1]);
                __half gy = __float2half_rn(vv.y * (1.f - th * th));
                __half2 hh = __halves2half2(gx, gy);
                stash[(f * 4 + g) * 2 + hr] = *reinterpret_cast<uint32_t*>(&hh);
            }
        }
    }
    mma_pass<NCHUNK, false>(zb, Z_LDH * 2, g_Bblk + (size_t)8 * CH_HALF,
                            g_BTblk, CH_BYTES, true,
                            bb, mb, ph0, ph1, acc);
    __syncthreads();
#pragma unroll
    for (int f = 0; f < 4; ++f) {
#pragma unroll
        for (int g = 0; g < 4; ++g) {
            const int n = wc * 32 + g * 8 + tg * 2;
#pragma unroll
            for (int hr = 0; hr < 2; ++hr) {
                const int ml = mbase + f * 16 + hr * 8;
                const int n2 = 256 + n;
                const int off = (f * 16 + hr * 8) * NSd + n2;
                float2 xa = *(const float2*)&xaRow[off];
                float2 vv = *(const float2*)&vRow[off];
                float th;
                th = tanh_ap(xa.x + acc[f][g][hr * 2 + 0]);
                __half gx = __float2half_rn(vv.x * (1.f - th * th));
                th = tanh_ap(xa.y + acc[f][g][hr * 2 + 1]);
                __half gy = __float2half_rn(vv.y * (1.f - th * th));
                *(__half2*)&smh[ml * Z_LDH + n2] = __halves2half2(gx, gy);
                *(__half2*)&smh[ml * Z_LDH + n] =
                    *reinterpret_cast<__half2*>(&stash[(f * 4 + g) * 2 + hr]);
            }
        }
    }

    // ---- vjp: vJ = g @ Bm ; sum of squares ----
    float ls = 0.f;
    mma_pass<NCHUNK, true>(zb, Z_LDH * 2, g_BTblk,
                           g_BTblk + (size_t)8 * CH_HALF, CH_BYTES, true,
                           bb, mb, ph0, ph1, acc);
#pragma unroll
    for (int f = 0; f < 4; ++f)
#pragma unroll
        for (int g = 0; g < 4; ++g)
#pragma unroll
            for (int r = 0; r < 4; ++r) ls += acc[f][g][r] * acc[f][g][r];
    mma_pass<NCHUNK, false>(zb, Z_LDH * 2, g_BTblk + (size_t)8 * CH_HALF,
                            (const __half*)0, 0, true,
                            bb, mb, ph0, ph1, acc);
#pragma unroll
    for (int f = 0; f < 4; ++f)
#pragma unroll
        for (int g = 0; g < 4; ++g)
#pragma unroll
            for (int r = 0; r < 4; ++r) ls += acc[f][g][r] * acc[f][g][r];

    float2 bs = block_reduce2(ls, 0.f);
    if (tid == 0) {
        g_jacpart[blockIdx.x] = bs.x;
        __threadfence();
        atomicAdd((unsigned*)(g_ecnt + 254), 1u);
    }

    // ---- CTA 0 finalizes jac_loss ----
    if (blockIdx.x == 0) {
        if (tid == 0) {
            while (g_ecnt[254] < (unsigned)GRID_IT) { }
            __threadfence();
        }
        __syncthreads();
        float s = (tid < GRID_IT) ? __ldcg((const float*)&g_jacpart[tid]) : 0.f;
        float2 tt = block_reduce2(s, 0.f);
        if (tid == 0) out[(size_t)NM * NOUT] = tt.x / ((float)NM * (float)NSd);
    }
}

// ---------------- launcher ----------------
extern "C" void kernel_launch(void* const* d_in, const int* in_sizes, int n_in,
                              void* d_out, int out_size) {
    const float* x   = (const float*)d_in[0];
    const float* A   = (const float*)d_in[1];
    const float* Bm  = (const float*)d_in[2];
    const float* b   = (const float*)d_in[3];
    const float* Wh  = (const float*)d_in[4];
    const float* bh  = (const float*)d_in[5];
    const float* v   = (const float*)d_in[6];
    float* out = (float*)d_out;

    static int configured = 0;
    if (!configured) {
        cudaFuncSetAttribute(k_iter, cudaFuncAttributeMaxDynamicSharedMemorySize, SMEM_DYN);
        configured = 1;
    }

    k_prep<<<4096, 256>>>(x, Bm, A, Wh);
    k_iter<<<GRID_IT, NTH_IT, SMEM_DYN>>>(b, v, bh, out);
}

// round 13
// speedup vs baseline: 1.1947x; 1.1329x over previous
#include <cuda_runtime.h>
#include <cuda_fp16.h>
#include <math.h>
#include <stdint.h>

#define NM    16384
#define NSd   512
#define NIN   64
#define NOUT  64
#define MAXITER   200
#define EPS_STOP  1e-3f

#define GRID_IT   128
#define NTH_IT    512                  // 16 warps
#define KC        64                   // K (halves) per B chunk
#define NCHUNK    8                    // 512 / 64
#define LDH       72                   // staged row pitch (halves)
#define LDB       (LDH * 2)            // 144 B
#define CH_HALF   (256 * LDH)          // 18432 halves per 256-row chunk block
#define CH_BYTES  (CH_HALF * 2)        // 36864 B
#define CHY_HALF  (64 * LDH)           // 4608 halves per 64-row chunk block
#define CHY_BYTES (CHY_HALF * 2)       // 9216 B
#define BSTAGE    CH_BYTES             // smem stage size
#define Z_LDH     520                  // z row pitch halves (1040 B)
#define Z_BYTES   (128 * Z_LDH * 2)    // 133120 B
#define MB_OFF    (Z_BYTES + 2 * BSTAGE)
#define SMEM_DYN  (MB_OFF + 64)        // + mbarrier area
#define XP        400                  // x-composite pitch bytes (200 halves)

// ---------------- device scratch (pre-baked padded operand blocks) ----------------
__device__ float  g_xA[NM * NSd];                       // x@A^T + b (fp32)
__device__ __align__(16) __half g_Bblk [2 * 8 * CH_HALF];   // Bm   [pass][chunk][256x72]
__device__ __align__(16) __half g_BTblk[2 * 8 * CH_HALF];   // Bm^T
__device__ __align__(16) __half g_Ablk [2 * 3 * CH_HALF];   // A-composite [pass][chunk][256x72]
__device__ __align__(16) __half g_Whb  [2 * 8 * CHY_HALF];  // Wh hi/lo [sel][chunk][64x72]
__device__ __align__(16) __half g_xPb  [NM * 200];          // x-composite rows, 200-half pitch
__device__ volatile unsigned g_ecnt[256];
__device__ float g_part[2][2 * GRID_IT];
__device__ float g_jacpart[GRID_IT];

// ---------------- helpers ----------------
__device__ __forceinline__ uint32_t smem_u32(const void* p) {
    uint32_t a;
    asm("{ .reg .u64 t; cvta.to.shared.u64 t, %1; cvt.u32.u64 %0, t; }" : "=r"(a) : "l"(p));
    return a;
}
__device__ __forceinline__ float tanh_ap(float x) {
    float y; asm("tanh.approx.f32 %0, %1;" : "=f"(y) : "f"(x)); return y;
}
__device__ __forceinline__ void ldmatrix_x4(uint32_t r[4], uint32_t addr) {
    asm volatile("ldmatrix.sync.aligned.m8n8.x4.shared.b16 {%0,%1,%2,%3}, [%4];"
        : "=r"(r[0]), "=r"(r[1]), "=r"(r[2]), "=r"(r[3]) : "r"(addr));
}
__device__ __forceinline__ void mma_f16(float c[4], const uint32_t a[4], const uint32_t b[2]) {
    asm volatile(
        "mma.sync.aligned.m16n8k16.row.col.f32.f16.f16.f32 "
        "{%0,%1,%2,%3}, {%4,%5,%6,%7}, {%8,%9}, {%0,%1,%2,%3};"
        : "+f"(c[0]), "+f"(c[1]), "+f"(c[2]), "+f"(c[3])
        : "r"(a[0]), "r"(a[1]), "r"(a[2]), "r"(a[3]), "r"(b[0]), "r"(b[1]));
}
#define MBAR_INIT(a, n) \
    asm volatile("mbarrier.init.shared.b64 [%0], %1;" :: "r"((uint32_t)(a)), "r"((uint32_t)(n)) : "memory")
#define MBAR_EXPECT_TX(a, nb) \
    asm volatile("mbarrier.arrive.expect_tx.shared.b64 _, [%0], %1;" :: "r"((uint32_t)(a)), "r"((uint32_t)(nb)) : "memory")
#define BULK_G2S(dst, src, nb, mbar) \
    asm volatile("cp.async.bulk.shared::cta.global.mbarrier::complete_tx::bytes [%0], [%1], %2, [%3];" \
        :: "r"((uint32_t)(dst)), "l"(src), "r"((uint32_t)(nb)), "r"((uint32_t)(mbar)) : "memory")
#define MBAR_WAIT(a, par) do {                                                             \
    uint32_t _m = (uint32_t)(a); uint32_t _p = (uint32_t)(par); uint32_t _d;               \
    asm volatile("{\n\t.reg .pred p;\n\t"                                                  \
        "mbarrier.try_wait.parity.acquire.cta.shared::cta.b64 p, [%1], %2;\n\t"            \
        "selp.b32 %0, 1, 0, p;\n\t}" : "=r"(_d) : "r"(_m), "r"(_p) : "memory");            \
    if (!_d) {                                                                             \
        asm volatile("{\n\t.reg .pred P1;\n\t"                                             \
            "WL_%=:\n\t"                                                                   \
            "mbarrier.try_wait.parity.acquire.cta.shared::cta.b64 P1, [%0], %1, 0x989680;\n\t" \
            "@P1 bra.uni WD_%=;\n\t"                                                       \
            "bra.uni WL_%=;\n\t"                                                           \
            "WD_%=:\n\t}" :: "r"(_m), "r"(_p) : "memory");                                 \
    }                                                                                      \
} while (0)

// Fused deterministic block reduce of two floats.
__device__ __forceinline__ float2 block_reduce2(float a, float b) {
    __shared__ float2 sr[16];
#pragma unroll
    for (int o = 16; o > 0; o >>= 1) {
        a += __shfl_xor_sync(0xFFFFFFFFu, a, o);
        b += __shfl_xor_sync(0xFFFFFFFFu, b, o);
    }
    const int w = threadIdx.x >> 5, lane = threadIdx.x & 31;
    __syncthreads();
    if (lane == 0) sr[w] = make_float2(a, b);
    __syncthreads();
    float2 t = make_float2(0.f, 0.f);
#pragma unroll
    for (int i = 0; i < 16; ++i) { t.x += sr[i].x; t.y += sr[i].y; }
    return t;
}

// ---------------- fp16 mma pass, A resident in SMEM, B via cp.async.bulk ----------------
template<int NC, bool SYNC>
__device__ void mma_pass(uint32_t aBase, int aPitchB,
                         const __half* __restrict__ Bblk,
                         const __half* __restrict__ preNext, uint32_t preBytes,
                         bool skipFirst,
                         uint32_t bb, uint32_t mb, int& ph0, int& ph1,
                         float acc[4][4][4]) {
    const int tid = threadIdx.x;
    const int w = tid >> 5, lane = tid & 31;
    const int wr = w >> 3, wc = w & 7;

#pragma unroll
    for (int f = 0; f < 4; ++f)
#pragma unroll
        for (int g = 0; g < 4; ++g)
#pragma unroll
            for (int r = 0; r < 4; ++r) acc[f][g][r] = 0.f;

    if (SYNC) __syncthreads();

    if (!skipFirst && tid == 0) {
        MBAR_EXPECT_TX(mb, CH_BYTES);
        BULK_G2S(bb, Bblk, CH_BYTES, mb);
    }

    const int rsel = lane & 15;
    const int ksel = (lane >> 4) << 3;
    const uint32_t arow = aBase + (uint32_t)((wr * 64 + rsel) * aPitchB);

    for (int c = 0; c < NC; ++c) {
        if ((c & 1) == 0) { MBAR_WAIT(mb, ph0 & 1); ph0++; }
        else              { MBAR_WAIT(mb + 8, ph1 & 1); ph1++; }
        __syncthreads();

        if (tid == 0) {
            if (c + 1 < NC) {
                const uint32_t m2 = mb + ((c + 1) & 1) * 8;
                MBAR_EXPECT_TX(m2, CH_BYTES);
                BULK_G2S(bb + ((c + 1) & 1) * BSTAGE, Bblk + (size_t)(c + 1) * CH_HALF,
                         CH_BYTES, m2);
            } else if (preNext) {
                const uint32_t m2 = mb + ((c + 1) & 1) * 8;
                MBAR_EXPECT_TX(m2, preBytes);
                BULK_G2S(bb + ((c + 1) & 1) * BSTAGE, preNext, preBytes, m2);
            }
        }

        const uint32_t sB = bb + (uint32_t)((c & 1) * BSTAGE);
#pragma unroll
        for (int ks = 0; ks < 4; ++ks) {
            const uint32_t koff = (uint32_t)((ks * 16 + ksel) * 2);
            const uint32_t akoff = (uint32_t)(c * (KC * 2)) + koff;
            uint32_t a[4][4], bf[2][4];
#pragma unroll
            for (int f = 0; f < 4; ++f)
                ldmatrix_x4(a[f], arow + (uint32_t)(f * 16 * aPitchB) + akoff);
#pragma unroll
            for (int h = 0; h < 2; ++h)
                ldmatrix_x4(bf[h], sB + (uint32_t)((wc * 32 + h * 16 + rsel) * LDB) + koff);
#pragma unroll
            for (int f = 0; f < 4; ++f) {
                { uint32_t b2[2] = {bf[0][0], bf[0][2]}; mma_f16(acc[f][0], a[f], b2); }
                { uint32_t b2[2] = {bf[0][1], bf[0][3]}; mma_f16(acc[f][1], a[f], b2); }
                { uint32_t b2[2] = {bf[1][0], bf[1][2]}; mma_f16(acc[f][2], a[f], b2); }
                { uint32_t b2[2] = {bf[1][1], bf[1][3]}; mma_f16(acc[f][3], a[f], b2); }
            }
        }
    }
}

// ---------------- y pass: acc[128x64] (+)= Z(128x512) @ Wh(64x512)^T ----------------
template<bool ZERO>
__device__ void mma_pass_y(uint32_t zb, const __half* __restrict__ Bblk,
                           const __half* __restrict__ preNext, uint32_t preBytes,
                           bool skipFirst,
                           uint32_t bb, uint32_t mb, int& ph0, int& ph1,
                           float acc[4][4]) {
    const int tid = threadIdx.x;
    const int w = tid >> 5, lane = tid & 31;
    const int wm = w >> 1, wn = w & 1;
    if (ZERO) {
#pragma unroll
        for (int g = 0; g < 4; ++g)
#pragma unroll
            for (int r = 0; r < 4; ++r) acc[g][r] = 0.f;
    }
    if (!skipFirst && tid == 0) {
        MBAR_EXPECT_TX(mb, CHY_BYTES);
        BULK_G2S(bb, Bblk, CHY_BYTES, mb);
    }
    const int rsel = lane & 15;
    const int ksel = (lane >> 4) << 3;
    const uint32_t arow = zb + (uint32_t)((wm * 16 + rsel) * (Z_LDH * 2));
    for (int c = 0; c < NCHUNK; ++c) {
        if ((c & 1) == 0) { MBAR_WAIT(mb, ph0 & 1); ph0++; }
        else              { MBAR_WAIT(mb + 8, ph1 & 1); ph1++; }
        __syncthreads();
        if (tid == 0) {
            if (c + 1 < NCHUNK) {
                const uint32_t m2 = mb + ((c + 1) & 1) * 8;
                MBAR_EXPECT_TX(m2, CHY_BYTES);
                BULK_G2S(bb + ((c + 1) & 1) * BSTAGE, Bblk + (size_t)(c + 1) * CHY_HALF,
                         CHY_BYTES, m2);
            } else if (preNext) {
                const uint32_t m2 = mb + ((c + 1) & 1) * 8;
                MBAR_EXPECT_TX(m2, preBytes);
                BULK_G2S(bb + ((c + 1) & 1) * BSTAGE, preNext, preBytes, m2);
            }
        }
        const uint32_t sB = bb + (uint32_t)((c & 1) * BSTAGE);
#pragma unroll
        for (int ks = 0; ks < 4; ++ks) {
            const uint32_t koff = (uint32_t)((ks * 16 + ksel) * 2);
            uint32_t a[4], bf[2][4];
            ldmatrix_x4(a, arow + (uint32_t)(c * (KC * 2)) + koff);
#pragma unroll
            for (int h = 0; h < 2; ++h)
                ldmatrix_x4(bf[h], sB + (uint32_t)((wn * 32 + h * 16 + rsel) * LDB) + koff);
            { uint32_t b2[2] = {bf[0][0], bf[0][2]}; mma_f16(acc[0], a, b2); }
            { uint32_t b2[2] = {bf[0][1], bf[0][3]}; mma_f16(acc[1], a, b2); }
            { uint32_t b2[2] = {bf[1][0], bf[1][2]}; mma_f16(acc[2], a, b2); }
            { uint32_t b2[2] = {bf[1][1], bf[1][3]}; mma_f16(acc[3], a, b2); }
        }
    }
}

// ---------------- k_prep: bake padded operand blocks ----------------
__global__ void k_prep(const float* __restrict__ x,
                       const float* __restrict__ Bm,
                       const float* __restrict__ A,
                       const float* __restrict__ Wh) {
    const int gid = blockIdx.x * 256 + threadIdx.x;
    const int NTOT = gridDim.x * 256;

    for (int d = gid; d < 2 * 8 * CH_HALF; d += NTOT) {
        const int col = d % LDH;
        const int r = (d / LDH) & 255;
        const int c = (d / (LDH * 256)) & 7;
        const int p = d / (LDH * 256 * 8);
        const int n = p * 256 + r;
        __half hv = __half(0), ht = __half(0);
        if (col < 64) {
            const int k = c * 64 + col;
            hv = __float2half_rn(Bm[n * NSd + k]);
            ht = __float2half_rn(Bm[k * NSd + n]);
        }
        g_Bblk[d] = hv;
        g_BTblk[d] = ht;
    }
    for (int d = gid; d < 2 * 3 * CH_HALF; d += NTOT) {
        const int col = d % LDH;
        const int r = (d / LDH) & 255;
        const int c = (d / (LDH * 256)) % 3;
        const int p = d / (LDH * 256 * 3);
        __half hv = __half(0);
        if (col < 64) {
            const float av = A[(p * 256 + r) * NIN + col];
            const __half hi = __float2half_rn(av);
            hv = (c == 2) ? __float2half_rn(av - __half2float(hi)) : hi;
        }
        g_Ablk[d] = hv;
    }
    for (int d = gid; d < 2 * 8 * CHY_HALF; d += NTOT) {
        const int col = d % LDH;
        const int r = (d / LDH) & 63;
        const int c = (d / (LDH * 64)) & 7;
        const int s = d / (LDH * 64 * 8);
        __half hv = __half(0);
        if (col < 64) {
            const float wv = Wh[r * NSd + c * 64 + col];
            const __half hi = __float2half_rn(wv);
            hv = s ? __float2half_rn(wv - __half2float(hi)) : hi;
        }
        g_Whb[d] = hv;
    }
    for (int d = gid; d < NM * 200; d += NTOT) {
        const int col = d % 200;
        const int m = d / 200;
        __half hv = __half(0);
        if (col < 192) {
            const int k = col & 63, s = col >> 6;
            const float xv = x[m * NIN + k];
            const __half hi = __float2half_rn(xv);
            hv = (s == 1) ? __float2half_rn(xv - __half2float(hi)) : hi;
        }
        g_xPb[d] = hv;
    }
    if (gid < 256) g_ecnt[gid] = 0u;
}

// ---------------- persistent solver ----------------
__global__ void __launch_bounds__(NTH_IT, 1) k_iter(const float* __restrict__ bvec,
                                                    const float* __restrict__ v,
                                                    const float* __restrict__ bhv,
                                                    float* __restrict__ out) {
    extern __shared__ __half smh[];
    const uint32_t zb = smem_u32(smh);
    const uint32_t bb = zb + (uint32_t)Z_BYTES;
    const uint32_t mb = zb + (uint32_t)MB_OFF;
    const uint32_t mbx = mb + 16;
    const int tid = threadIdx.x;
    const int w = tid >> 5, lane = tid & 31;
    const int wr = w >> 3, wc = w & 7;
    const int grp = lane >> 2, tg = lane & 3;
    const int m0 = blockIdx.x * 128;
    float acc[4][4][4];
    uint32_t stash[32];
    int ph0 = 0, ph1 = 0;

    if (tid == 0) { MBAR_INIT(mb, 1); MBAR_INIT(mb + 8, 1); MBAR_INIT(mbx, 1); }
    __syncthreads();

    const int mbase = wr * 64 + grp;
    float* xaRow = g_xA + (size_t)(m0 + mbase) * NSd;

    // ---- xA phase: composite x (K=192) -> exact-grade xA; z1 = tanh(xA) ----
    {
        if (tid == 0) {
            MBAR_EXPECT_TX(mbx, 128 * XP);
            BULK_G2S(zb, g_xPb + (size_t)m0 * 200, 128 * XP, mbx);
        }
        MBAR_WAIT(mbx, 0);

        mma_pass<3, true>(zb, XP, g_Ablk, (const __half*)0, 0, false,
                          bb, mb, ph0, ph1, acc);
#pragma unroll
        for (int f = 0; f < 4; ++f) {
#pragma unroll
            for (int g = 0; g < 4; ++g) {
                const int n = wc * 32 + g * 8 + tg * 2;
                float2 b2 = *(const float2*)&bvec[n];
#pragma unroll
                for (int hr = 0; hr < 2; ++hr) {
                    const int off = (f * 16 + hr * 8) * NSd + n;
                    const float xx = acc[f][g][hr * 2 + 0] + b2.x;
                    const float xy = acc[f][g][hr * 2 + 1] + b2.y;
                    *(float2*)&xaRow[off] = make_float2(xx, xy);
                    __half2 hh = __floats2half2_rn(tanh_ap(xx), tanh_ap(xy));
                    stash[(f * 4 + g) * 2 + hr] = *reinterpret_cast<uint32_t*>(&hh);
                }
            }
        }
        mma_pass<3, true>(zb, XP, g_Ablk + (size_t)3 * CH_HALF, (const __half*)0, 0, false,
                          bb, mb, ph0, ph1, acc);
        __syncthreads();   // pass-1 GEMM reads of x-tile done -> overwrite with z
#pragma unroll
        for (int f = 0; f < 4; ++f) {
#pragma unroll
            for (int g = 0; g < 4; ++g) {
                const int n = wc * 32 + g * 8 + tg * 2;
                float2 b2 = *(const float2*)&bvec[256 + n];
#pragma unroll
                for (int hr = 0; hr < 2; ++hr) {
                    const int ml = mbase + f * 16 + hr * 8;
                    const int off = (f * 16 + hr * 8) * NSd + 256 + n;
                    const float xx = acc[f][g][hr * 2 + 0] + b2.x;
                    const float xy = acc[f][g][hr * 2 + 1] + b2.y;
                    *(float2*)&xaRow[off] = make_float2(xx, xy);
                    *(__half2*)&smh[ml * Z_LDH + 256 + n] =
                        __floats2half2_rn(tanh_ap(xx), tanh_ap(xy));
                    *(__half2*)&smh[ml * Z_LDH + n] =
                        *reinterpret_cast<__half2*>(&stash[(f * 4 + g) * 2 + hr]);
                }
            }
        }
    }

    // ---- iterations t = 2..MAXITER; prefetch-chained passes, lagged stop ----
    for (int t = 2; t <= MAXITER; ++t) {
        float lnum = 0.f, lden = 0.f;

        mma_pass<NCHUNK, true>(zb, Z_LDH * 2, g_Bblk,
                               g_Bblk + (size_t)8 * CH_HALF, CH_BYTES, t != 2,
                               bb, mb, ph0, ph1, acc);
#pragma unroll
        for (int f = 0; f < 4; ++f) {
#pragma unroll
            for (int g = 0; g < 4; ++g) {
                const int n = wc * 32 + g * 8 + tg * 2;
#pragma unroll
                for (int hr = 0; hr < 2; ++hr) {
                    const int ml = mbase + f * 16 + hr * 8;
                    float2 xa = *(const float2*)&xaRow[(f * 16 + hr * 8) * NSd + n];
                    __half2 hh = __floats2half2_rn(tanh_ap(xa.x + acc[f][g][hr * 2 + 0]),
                                                   tanh_ap(xa.y + acc[f][g][hr * 2 + 1]));
                    const float zx = __low2float(hh), zy = __high2float(hh);
                    __half2 zp = *(__half2*)&smh[ml * Z_LDH + n];
                    const float dx = zx - __low2float(zp);
                    const float dy = zy - __high2float(zp);
                    lnum += dx * dx + dy * dy;
                    lden += zx * zx + zy * zy;
                    stash[(f * 4 + g) * 2 + hr] = *reinterpret_cast<uint32_t*>(&hh);
                }
            }
        }
        // pass1 preloads g_Bblk chunk 0 — correct when iterating again; discarded
        // before the y-pass on stop.
        mma_pass<NCHUNK, false>(zb, Z_LDH * 2, g_Bblk + (size_t)8 * CH_HALF,
                                g_Bblk, CH_BYTES, true,
                                bb, mb, ph0, ph1, acc);
        __syncthreads();   // GEMM reads of z done -> overwrite
#pragma unroll
        for (int f = 0; f < 4; ++f) {
#pragma unroll
            for (int g = 0; g < 4; ++g) {
                const int n = wc * 32 + g * 8 + tg * 2;
#pragma unroll
                for (int hr = 0; hr < 2; ++hr) {
                    const int ml = mbase + f * 16 + hr * 8;
                    const int n2 = 256 + n;
                    float2 xa = *(const float2*)&xaRow[(f * 16 + hr * 8) * NSd + n2];
                    __half2 hh = __floats2half2_rn(tanh_ap(xa.x + acc[f][g][hr * 2 + 0]),
                                                   tanh_ap(xa.y + acc[f][g][hr * 2 + 1]));
                    const float zx = __low2float(hh), zy = __high2float(hh);
                    __half2 zp = *(__half2*)&smh[ml * Z_LDH + n2];
                    const float dx = zx - __low2float(zp);
                    const float dy = zy - __high2float(zp);
                    lnum += dx * dx + dy * dy;
                    lden += zx * zx + zy * zy;
                    *(__half2*)&smh[ml * Z_LDH + n2] = hh;
                    *(__half2*)&smh[ml * Z_LDH + n] =
                        *reinterpret_cast<__half2*>(&stash[(f * 4 + g) * 2 + hr]);
                }
            }
        }

        float2 bpart = block_reduce2(lnum, lden);
        if (tid == 0) {
            g_part[t & 1][2 * blockIdx.x]     = bpart.x;
            g_part[t & 1][2 * blockIdx.x + 1] = bpart.y;
            __threadfence();
            if (t > 2) {
                while (g_ecnt[t - 1] < (unsigned)GRID_IT) { }
                __threadfence();
            }
        }
        __syncthreads();

        bool stop = false;
        if (t > 2) {
            float pn = 0.f, pd = 0.f;
            if (tid < GRID_IT) {
                float2 pp = __ldcg((const float2*)&g_part[(t - 1) & 1][2 * tid]);
                pn = pp.x; pd = pp.y;
            }
            float2 tot = block_reduce2(pn, pd);
            const float res = sqrtf(tot.x) / (sqrtf(tot.y) + 1e-8f);
            stop = (res <= EPS_STOP);
        }
        __syncthreads();
        if (tid == 0) atomicAdd((unsigned*)(g_ecnt + t), 1u);
        if (stop) break;
    }

    // Discard the speculative g_Bblk chunk-0 preload: consume its arrival.
    MBAR_WAIT(mb, ph0 & 1); ph0++;

    // ---- y = z* @ Wh^T + bh (hi/lo split), written directly to out ----
    // y-lo preloads BTblk chunk 0 so the vjp starts hot.
    {
        float yacc[4][4];
        mma_pass_y<true >(zb, g_Whb, g_Whb + (size_t)8 * CHY_HALF, CHY_BYTES, false,
                          bb, mb, ph0, ph1, yacc);
        mma_pass_y<false>(zb, g_Whb + (size_t)8 * CHY_HALF, g_BTblk, CH_BYTES, true,
                          bb, mb, ph0, ph1, yacc);
        const int wm = w >> 1, wn = w & 1;
#pragma unroll
        for (int g = 0; g < 4; ++g) {
            const int col = wn * 32 + g * 8 + tg * 2;
            float2 b2 = *(const float2*)&bhv[col];
#pragma unroll
            for (int hr = 0; hr < 2; ++hr) {
                const int m = m0 + wm * 16 + grp + hr * 8;
                *(float2*)&out[(size_t)m * NOUT + col] =
                    make_float2(yacc[g][hr * 2] + b2.x, yacc[g][hr * 2 + 1] + b2.y);
            }
        }
    }

    // ---- g = v * (1 - z*^2) elementwise (fixed-point identity tanh(f-arg) = z*),
    //      overwriting z in smem. No GEMM needed. ----
    __syncthreads();   // y-pass GEMM reads of z complete
    {
        const int npairs = (128 * NSd) / 2;   // 32768 half2 per CTA
        for (int i = tid; i < npairs; i += NTH_IT) {
            const int row = i >> 8;           // 256 pairs per row
            const int cp = i & 255;
            __half2 zz = *(__half2*)&smh[row * Z_LDH + cp * 2];
            float2 vv = *(const float2*)&v[(size_t)(m0 + row) * NSd + cp * 2];
            const float zx = __low2float(zz), zy = __high2float(zz);
            *(__half2*)&smh[row * Z_LDH + cp * 2] =
                __floats2half2_rn(vv.x * (1.f - zx * zx), vv.y * (1.f - zy * zy));
        }
    }

    // ---- vjp: vJ = g @ Bm ; sum of squares ----
    float ls = 0.f;
    mma_pass<NCHUNK, true>(zb, Z_LDH * 2, g_BTblk,
                           g_BTblk + (size_t)8 * CH_HALF, CH_BYTES, true,
                           bb, mb, ph0, ph1, acc);
#pragma unroll
    for (int f = 0; f < 4; ++f)
#pragma unroll
        for (int g = 0; g < 4; ++g)
#pragma unroll
            for (int r = 0; r < 4; ++r) ls += acc[f][g][r] * acc[f][g][r];
    mma_pass<NCHUNK, false>(zb, Z_LDH * 2, g_BTblk + (size_t)8 * CH_HALF,
                            (const __half*)0, 0, true,
                            bb, mb, ph0, ph1, acc);
#pragma unroll
    for (int f = 0; f < 4; ++f)
#pragma unroll
        for (int g = 0; g < 4; ++g)
#pragma unroll
            for (int r = 0; r < 4; ++r) ls += acc[f][g][r] * acc[f][g][r];

    float2 bs = block_reduce2(ls, 0.f);
    if (tid == 0) {
        g_jacpart[blockIdx.x] = bs.x;
        __threadfence();
        atomicAdd((unsigned*)(g_ecnt + 254), 1u);
    }

    // ---- CTA 0 finalizes jac_loss ----
    if (blockIdx.x == 0) {
        if (tid == 0) {
            while (g_ecnt[254] < (unsigned)GRID_IT) { }
            __threadfence();
        }
        __syncthreads();
        float s = (tid < GRID_IT) ? __ldcg((const float*)&g_jacpart[tid]) : 0.f;
        float2 tt = block_reduce2(s, 0.f);
        if (tid == 0) out[(size_t)NM * NOUT] = tt.x / ((float)NM * (float)NSd);
    }
}

// ---------------- launcher ----------------
extern "C" void kernel_launch(void* const* d_in, const int* in_sizes, int n_in,
                              void* d_out, int out_size) {
    const float* x   = (const float*)d_in[0];
    const float* A   = (const float*)d_in[1];
    const float* Bm  = (const float*)d_in[2];
    const float* b   = (const float*)d_in[3];
    const float* Wh  = (const float*)d_in[4];
    const float* bh  = (const float*)d_in[5];
    const float* v   = (const float*)d_in[6];
    float* out = (float*)d_out;

    static int configured = 0;
    if (!configured) {
        cudaFuncSetAttribute(k_iter, cudaFuncAttributeMaxDynamicSharedMemorySize, SMEM_DYN);
        configured = 1;
    }

    k_prep<<<4096, 256>>>(x, Bm, A, Wh);
    k_iter<<<GRID_IT, NTH_IT, SMEM_DYN>>>(b, v, bh, out);
}

// round 16
// speedup vs baseline: 1.2043x; 1.0080x over previous
#include <cuda_runtime.h>
#include <cuda_fp16.h>
#include <math.h>
#include <stdint.h>

#define NM    16384
#define NSd   512
#define NIN   64
#define NOUT  64
#define MAXITER   200
#define EPS_STOP  1e-3f

#define GRID_IT   128
#define NTH_IT    512                  // 16 warps
#define KC        64                   // K (halves) per B chunk
#define NCHUNK    8                    // 512 / 64
#define LDH       72                   // staged row pitch (halves)
#define LDB       (LDH * 2)            // 144 B
#define CH_HALF   (256 * LDH)          // 18432 halves per 256-row chunk block
#define CH_BYTES  (CH_HALF * 2)        // 36864 B
#define CHY_HALF  (64 * LDH)           // 4608 halves per 64-row chunk block
#define CHY_BYTES (CHY_HALF * 2)       // 9216 B
#define BSTAGE    CH_BYTES             // smem stage size
#define Z_LDH     520                  // z row pitch halves (1040 B)
#define Z_BYTES   (128 * Z_LDH * 2)    // 133120 B
#define MB_OFF    (Z_BYTES + 2 * BSTAGE)
#define SMEM_DYN  (MB_OFF + 64)        // + mbarrier area
#define XP        400                  // x-composite pitch bytes (200 halves)

// ---------------- device scratch (pre-baked padded operand blocks) ----------------
__device__ float  g_xA[NM * NSd];                       // x@A^T + b (fp32)
__device__ __align__(16) __half g_Bblk [2 * 8 * CH_HALF];   // Bm   [pass][chunk][256x72]
__device__ __align__(16) __half g_BTblk[2 * 8 * CH_HALF];   // Bm^T
__device__ __align__(16) __half g_Ablk [2 * 3 * CH_HALF];   // A-composite [pass][chunk][256x72]
__device__ __align__(16) __half g_Whb  [2 * 8 * CHY_HALF];  // Wh hi/lo [sel][chunk][64x72]
__device__ __align__(16) __half g_xPb  [NM * 200];          // x-composite rows, 200-half pitch
__device__ volatile unsigned g_ecnt[256];
__device__ float g_part[2][2 * GRID_IT];
__device__ float g_jacpart[GRID_IT];

// ---------------- helpers ----------------
__device__ __forceinline__ uint32_t smem_u32(const void* p) {
    uint32_t a;
    asm("{ .reg .u64 t; cvta.to.shared.u64 t, %1; cvt.u32.u64 %0, t; }" : "=r"(a) : "l"(p));
    return a;
}
__device__ __forceinline__ float tanh_ap(float x) {
    float y; asm("tanh.approx.f32 %0, %1;" : "=f"(y) : "f"(x)); return y;
}
__device__ __forceinline__ void ldmatrix_x4(uint32_t r[4], uint32_t addr) {
    asm volatile("ldmatrix.sync.aligned.m8n8.x4.shared.b16 {%0,%1,%2,%3}, [%4];"
        : "=r"(r[0]), "=r"(r[1]), "=r"(r[2]), "=r"(r[3]) : "r"(addr));
}
__device__ __forceinline__ void mma_f16(float c[4], const uint32_t a[4], const uint32_t b[2]) {
    asm volatile(
        "mma.sync.aligned.m16n8k16.row.col.f32.f16.f16.f32 "
        "{%0,%1,%2,%3}, {%4,%5,%6,%7}, {%8,%9}, {%0,%1,%2,%3};"
        : "+f"(c[0]), "+f"(c[1]), "+f"(c[2]), "+f"(c[3])
        : "r"(a[0]), "r"(a[1]), "r"(a[2]), "r"(a[3]), "r"(b[0]), "r"(b[1]));
}
#define MBAR_INIT(a, n) \
    asm volatile("mbarrier.init.shared.b64 [%0], %1;" :: "r"((uint32_t)(a)), "r"((uint32_t)(n)) : "memory")
#define MBAR_EXPECT_TX(a, nb) \
    asm volatile("mbarrier.arrive.expect_tx.shared.b64 _, [%0], %1;" :: "r"((uint32_t)(a)), "r"((uint32_t)(nb)) : "memory")
#define BULK_G2S(dst, src, nb, mbar) \
    asm volatile("cp.async.bulk.shared::cta.global.mbarrier::complete_tx::bytes [%0], [%1], %2, [%3];" \
        :: "r"((uint32_t)(dst)), "l"(src), "r"((uint32_t)(nb)), "r"((uint32_t)(mbar)) : "memory")
#define MBAR_WAIT(a, par) do {                                                             \
    uint32_t _m = (uint32_t)(a); uint32_t _p = (uint32_t)(par); uint32_t _d;               \
    asm volatile("{\n\t.reg .pred p;\n\t"                                                  \
        "mbarrier.try_wait.parity.acquire.cta.shared::cta.b64 p, [%1], %2;\n\t"            \
        "selp.b32 %0, 1, 0, p;\n\t}" : "=r"(_d) : "r"(_m), "r"(_p) : "memory");            \
    if (!_d) {                                                                             \
        asm volatile("{\n\t.reg .pred P1;\n\t"                                             \
            "WL_%=:\n\t"                                                                   \
            "mbarrier.try_wait.parity.acquire.cta.shared::cta.b64 P1, [%0], %1, 0x989680;\n\t" \
            "@P1 bra.uni WD_%=;\n\t"                                                       \
            "bra.uni WL_%=;\n\t"                                                           \
            "WD_%=:\n\t}" :: "r"(_m), "r"(_p) : "memory");                                 \
    }                                                                                      \
} while (0)

// Fused deterministic block reduce of two floats.
__device__ __forceinline__ float2 block_reduce2(float a, float b) {
    __shared__ float2 sr[16];
#pragma unroll
    for (int o = 16; o > 0; o >>= 1) {
        a += __shfl_xor_sync(0xFFFFFFFFu, a, o);
        b += __shfl_xor_sync(0xFFFFFFFFu, b, o);
    }
    const int w = threadIdx.x >> 5, lane = threadIdx.x & 31;
    __syncthreads();
    if (lane == 0) sr[w] = make_float2(a, b);
    __syncthreads();
    float2 t = make_float2(0.f, 0.f);
#pragma unroll
    for (int i = 0; i < 16; ++i) { t.x += sr[i].x; t.y += sr[i].y; }
    return t;
}

// ---------------- fp16 mma pass, A resident in SMEM, B via cp.async.bulk ----------------
template<int NC, bool SYNC>
__device__ void mma_pass(uint32_t aBase, int aPitchB,
                         const __half* __restrict__ Bblk,
                         const __half* __restrict__ preNext, uint32_t preBytes,
                         bool skipFirst,
                         uint32_t bb, uint32_t mb, int& ph0, int& ph1,
                         float acc[4][4][4]) {
    const int tid = threadIdx.x;
    const int w = tid >> 5, lane = tid & 31;
    const int wr = w >> 3, wc = w & 7;

#pragma unroll
    for (int f = 0; f < 4; ++f)
#pragma unroll
        for (int g = 0; g < 4; ++g)
#pragma unroll
            for (int r = 0; r < 4; ++r) acc[f][g][r] = 0.f;

    if (SYNC) __syncthreads();

    if (!skipFirst && tid == 0) {
        MBAR_EXPECT_TX(mb, CH_BYTES);
        BULK_G2S(bb, Bblk, CH_BYTES, mb);
    }

    const int rsel = lane & 15;
    const int ksel = (lane >> 4) << 3;
    const uint32_t arow = aBase + (uint32_t)((wr * 64 + rsel) * aPitchB);

    for (int c = 0; c < NC; ++c) {
        if ((c & 1) == 0) { MBAR_WAIT(mb, ph0 & 1); ph0++; }
        else              { MBAR_WAIT(mb + 8, ph1 & 1); ph1++; }
        __syncthreads();

        if (tid == 0) {
            if (c + 1 < NC) {
                const uint32_t m2 = mb + ((c + 1) & 1) * 8;
                MBAR_EXPECT_TX(m2, CH_BYTES);
                BULK_G2S(bb + ((c + 1) & 1) * BSTAGE, Bblk + (size_t)(c + 1) * CH_HALF,
                         CH_BYTES, m2);
            } else if (preNext) {
                const uint32_t m2 = mb + ((c + 1) & 1) * 8;
                MBAR_EXPECT_TX(m2, preBytes);
                BULK_G2S(bb + ((c + 1) & 1) * BSTAGE, preNext, preBytes, m2);
            }
        }

        const uint32_t sB = bb + (uint32_t)((c & 1) * BSTAGE);
#pragma unroll
        for (int ks = 0; ks < 4; ++ks) {
            const uint32_t koff = (uint32_t)((ks * 16 + ksel) * 2);
            const uint32_t akoff = (uint32_t)(c * (KC * 2)) + koff;
            uint32_t a[4][4], bf[2][4];
#pragma unroll
            for (int f = 0; f < 4; ++f)
                ldmatrix_x4(a[f], arow + (uint32_t)(f * 16 * aPitchB) + akoff);
#pragma unroll
            for (int h = 0; h < 2; ++h)
                ldmatrix_x4(bf[h], sB + (uint32_t)((wc * 32 + h * 16 + rsel) * LDB) + koff);
#pragma unroll
            for (int f = 0; f < 4; ++f) {
                { uint32_t b2[2] = {bf[0][0], bf[0][2]}; mma_f16(acc[f][0], a[f], b2); }
                { uint32_t b2[2] = {bf[0][1], bf[0][3]}; mma_f16(acc[f][1], a[f], b2); }
                { uint32_t b2[2] = {bf[1][0], bf[1][2]}; mma_f16(acc[f][2], a[f], b2); }
                { uint32_t b2[2] = {bf[1][1], bf[1][3]}; mma_f16(acc[f][3], a[f], b2); }
            }
        }
    }
}

// ---------------- y pass: acc[128x64] (+)= Z(128x512) @ Wh(64x512)^T ----------------
template<bool ZERO>
__device__ void mma_pass_y(uint32_t zb, const __half* __restrict__ Bblk,
                           const __half* __restrict__ preNext, uint32_t preBytes,
                           bool skipFirst,
                           uint32_t bb, uint32_t mb, int& ph0, int& ph1,
                           float acc[4][4]) {
    const int tid = threadIdx.x;
    const int w = tid >> 5, lane = tid & 31;
    const int wm = w >> 1, wn = w & 1;
    if (ZERO) {
#pragma unroll
        for (int g = 0; g < 4; ++g)
#pragma unroll
            for (int r = 0; r < 4; ++r) acc[g][r] = 0.f;
    }
    if (!skipFirst && tid == 0) {
        MBAR_EXPECT_TX(mb, CHY_BYTES);
        BULK_G2S(bb, Bblk, CHY_BYTES, mb);
    }
    const int rsel = lane & 15;
    const int ksel = (lane >> 4) << 3;
    const uint32_t arow = zb + (uint32_t)((wm * 16 + rsel) * (Z_LDH * 2));
    for (int c = 0; c < NCHUNK; ++c) {
        if ((c & 1) == 0) { MBAR_WAIT(mb, ph0 & 1); ph0++; }
        else              { MBAR_WAIT(mb + 8, ph1 & 1); ph1++; }
        __syncthreads();
        if (tid == 0) {
            if (c + 1 < NCHUNK) {
                const uint32_t m2 = mb + ((c + 1) & 1) * 8;
                MBAR_EXPECT_TX(m2, CHY_BYTES);
                BULK_G2S(bb + ((c + 1) & 1) * BSTAGE, Bblk + (size_t)(c + 1) * CHY_HALF,
                         CHY_BYTES, m2);
            } else if (preNext) {
                const uint32_t m2 = mb + ((c + 1) & 1) * 8;
                MBAR_EXPECT_TX(m2, preBytes);
                BULK_G2S(bb + ((c + 1) & 1) * BSTAGE, preNext, preBytes, m2);
            }
        }
        const uint32_t sB = bb + (uint32_t)((c & 1) * BSTAGE);
#pragma unroll
        for (int ks = 0; ks < 4; ++ks) {
            const uint32_t koff = (uint32_t)((ks * 16 + ksel) * 2);
            uint32_t a[4], bf[2][4];
            ldmatrix_x4(a, arow + (uint32_t)(c * (KC * 2)) + koff);
#pragma unroll
            for (int h = 0; h < 2; ++h)
                ldmatrix_x4(bf[h], sB + (uint32_t)((wn * 32 + h * 16 + rsel) * LDB) + koff);
            { uint32_t b2[2] = {bf[0][0], bf[0][2]}; mma_f16(acc[0], a, b2); }
            { uint32_t b2[2] = {bf[0][1], bf[0][3]}; mma_f16(acc[1], a, b2); }
            { uint32_t b2[2] = {bf[1][0], bf[1][2]}; mma_f16(acc[2], a, b2); }
            { uint32_t b2[2] = {bf[1][1], bf[1][3]}; mma_f16(acc[3], a, b2); }
        }
    }
}

// ---------------- k_prep: bake padded operand blocks (vectorized) ----------------
__global__ void k_prep(const float* __restrict__ x,
                       const float* __restrict__ Bm,
                       const float* __restrict__ A,
                       const float* __restrict__ Wh) {
    const int gid = blockIdx.x * 256 + threadIdx.x;
    const int NTOT = gridDim.x * 256;

    // Bm and Bm^T blocks, half2-vectorized: 8*CH_HALF half2 units cover both passes
    for (int u = gid; u < 8 * CH_HALF; u += NTOT) {
        const int col2 = u % 36;
        const int rest = u / 36;                 // 0..4095
        const int r = rest & 255;
        const int c = (rest >> 8) & 7;
        const int p = rest >> 11;
        const int n = p * 256 + r;
        __half2 hv = __halves2half2(__half(0), __half(0));
        __half2 ht = hv;
        if (col2 < 32) {
            const int k = c * 64 + col2 * 2;
            float2 bv = *(const float2*)&Bm[n * NSd + k];
            hv = __floats2half2_rn(bv.x, bv.y);
            ht = __halves2half2(__float2half_rn(Bm[k * NSd + n]),
                                __float2half_rn(Bm[(k + 1) * NSd + n]));
        }
        *(__half2*)&g_Bblk[(size_t)u * 2] = hv;
        *(__half2*)&g_BTblk[(size_t)u * 2] = ht;
    }
    // A-composite blocks (small, scalar)
    for (int d = gid; d < 2 * 3 * CH_HALF; d += NTOT) {
        const int col = d % LDH;
        const int r = (d / LDH) & 255;
        const int c = (d / (LDH * 256)) % 3;
        const int p = d / (LDH * 256 * 3);
        __half hv = __half(0);
        if (col < 64) {
            const float av = A[(p * 256 + r) * NIN + col];
            const __half hi = __float2half_rn(av);
            hv = (c == 2) ? __float2half_rn(av - __half2float(hi)) : hi;
        }
        g_Ablk[d] = hv;
    }
    // Wh hi/lo blocks (small, scalar)
    for (int d = gid; d < 2 * 8 * CHY_HALF; d += NTOT) {
        const int col = d % LDH;
        const int r = (d / LDH) & 63;
        const int c = (d / (LDH * 64)) & 7;
        const int s = d / (LDH * 64 * 8);
        __half hv = __half(0);
        if (col < 64) {
            const float wv = Wh[r * NSd + c * 64 + col];
            const __half hi = __float2half_rn(wv);
            hv = s ? __float2half_rn(wv - __half2float(hi)) : hi;
        }
        g_Whb[d] = hv;
    }
    // x-composite rows, half2-vectorized: [hi(64)|lo(64)|hi(64)|pad(8)]
    for (int u = gid; u < NM * 100; u += NTOT) {
        const int col2 = u % 100;
        const int m = u / 100;
        __half2 hv = __halves2half2(__half(0), __half(0));
        if (col2 < 96) {
            const int col = col2 * 2;
            const int s = col >> 6, k = col & 63;
            float2 xv = *(const float2*)&x[m * NIN + k];
            __half2 hi2 = __floats2half2_rn(xv.x, xv.y);
            if (s == 1) {
                hv = __floats2half2_rn(xv.x - __half2float(__low2half(hi2)),
                                       xv.y - __half2float(__high2half(hi2)));
            } else hv = hi2;
        }
        *(__half2*)&g_xPb[(size_t)m * 200 + col2 * 2] = hv;
    }
    if (gid < 256) g_ecnt[gid] = 0u;
}

// ---------------- persistent solver (R13-proven control flow) ----------------
__global__ void __launch_bounds__(NTH_IT, 1) k_iter(const float* __restrict__ bvec,
                                                    const float* __restrict__ v,
                                                    const float* __restrict__ bhv,
                                                    float* __restrict__ out) {
    extern __shared__ __half smh[];
    const uint32_t zb = smem_u32(smh);
    const uint32_t bb = zb + (uint32_t)Z_BYTES;
    const uint32_t mb = zb + (uint32_t)MB_OFF;
    const uint32_t mbx = mb + 16;
    const int tid = threadIdx.x;
    const int w = tid >> 5, lane = tid & 31;
    const int wr = w >> 3, wc = w & 7;
    const int grp = lane >> 2, tg = lane & 3;
    const int m0 = blockIdx.x * 128;
    float acc[4][4][4];
    uint32_t stash[32];
    int ph0 = 0, ph1 = 0;

    if (tid == 0) { MBAR_INIT(mb, 1); MBAR_INIT(mb + 8, 1); MBAR_INIT(mbx, 1); }
    __syncthreads();

    const int mbase = wr * 64 + grp;
    float* xaRow = g_xA + (size_t)(m0 + mbase) * NSd;

    // ---- xA phase: composite x (K=192) -> exact-grade xA; z1 = tanh(xA) ----
    {
        if (tid == 0) {
            MBAR_EXPECT_TX(mbx, 128 * XP);
            BULK_G2S(zb, g_xPb + (size_t)m0 * 200, 128 * XP, mbx);
        }
        MBAR_WAIT(mbx, 0);

        mma_pass<3, true>(zb, XP, g_Ablk, (const __half*)0, 0, false,
                          bb, mb, ph0, ph1, acc);
#pragma unroll
        for (int f = 0; f < 4; ++f) {
#pragma unroll
            for (int g = 0; g < 4; ++g) {
                const int n = wc * 32 + g * 8 + tg * 2;
                float2 b2 = *(const float2*)&bvec[n];
#pragma unroll
                for (int hr = 0; hr < 2; ++hr) {
                    const int off = (f * 16 + hr * 8) * NSd + n;
                    const float xx = acc[f][g][hr * 2 + 0] + b2.x;
                    const float xy = acc[f][g][hr * 2 + 1] + b2.y;
                    *(float2*)&xaRow[off] = make_float2(xx, xy);
                    __half2 hh = __floats2half2_rn(tanh_ap(xx), tanh_ap(xy));
                    stash[(f * 4 + g) * 2 + hr] = *reinterpret_cast<uint32_t*>(&hh);
                }
            }
        }
        mma_pass<3, true>(zb, XP, g_Ablk + (size_t)3 * CH_HALF, (const __half*)0, 0, false,
                          bb, mb, ph0, ph1, acc);
        __syncthreads();   // pass-1 GEMM reads of x-tile done -> overwrite with z
#pragma unroll
        for (int f = 0; f < 4; ++f) {
#pragma unroll
            for (int g = 0; g < 4; ++g) {
                const int n = wc * 32 + g * 8 + tg * 2;
                float2 b2 = *(const float2*)&bvec[256 + n];
#pragma unroll
                for (int hr = 0; hr < 2; ++hr) {
                    const int ml = mbase + f * 16 + hr * 8;
                    const int off = (f * 16 + hr * 8) * NSd + 256 + n;
                    const float xx = acc[f][g][hr * 2 + 0] + b2.x;
                    const float xy = acc[f][g][hr * 2 + 1] + b2.y;
                    *(float2*)&xaRow[off] = make_float2(xx, xy);
                    *(__half2*)&smh[ml * Z_LDH + 256 + n] =
                        __floats2half2_rn(tanh_ap(xx), tanh_ap(xy));
                    *(__half2*)&smh[ml * Z_LDH + n] =
                        *reinterpret_cast<__half2*>(&stash[(f * 4 + g) * 2 + hr]);
                }
            }
        }
    }

    // ---- iterations t = 2..MAXITER; prefetch-chained passes, lagged stop ----
    for (int t = 2; t <= MAXITER; ++t) {
        float lnum = 0.f, lden = 0.f;

        mma_pass<NCHUNK, true>(zb, Z_LDH * 2, g_Bblk,
                               g_Bblk + (size_t)8 * CH_HALF, CH_BYTES, t != 2,
                               bb, mb, ph0, ph1, acc);
#pragma unroll
        for (int f = 0; f < 4; ++f) {
#pragma unroll
            for (int g = 0; g < 4; ++g) {
                const int n = wc * 32 + g * 8 + tg * 2;
#pragma unroll
                for (int hr = 0; hr < 2; ++hr) {
                    const int ml = mbase + f * 16 + hr * 8;
                    float2 xa = *(const float2*)&xaRow[(f * 16 + hr * 8) * NSd + n];
                    __half2 hh = __floats2half2_rn(tanh_ap(xa.x + acc[f][g][hr * 2 + 0]),
                                                   tanh_ap(xa.y + acc[f][g][hr * 2 + 1]));
                    const float zx = __low2float(hh), zy = __high2float(hh);
                    __half2 zp = *(__half2*)&smh[ml * Z_LDH + n];
                    const float dx = zx - __low2float(zp);
                    const float dy = zy - __high2float(zp);
                    lnum += dx * dx + dy * dy;
                    lden += zx * zx + zy * zy;
                    stash[(f * 4 + g) * 2 + hr] = *reinterpret_cast<uint32_t*>(&hh);
                }
            }
        }
        // pass1 preloads g_Bblk chunk 0 — correct when iterating again; discarded
        // before the y-pass on stop.
        mma_pass<NCHUNK, false>(zb, Z_LDH * 2, g_Bblk + (size_t)8 * CH_HALF,
                                g_Bblk, CH_BYTES, true,
                                bb, mb, ph0, ph1, acc);
        __syncthreads();   // GEMM reads of z done -> overwrite
#pragma unroll
        for (int f = 0; f < 4; ++f) {
#pragma unroll
            for (int g = 0; g < 4; ++g) {
                const int n = wc * 32 + g * 8 + tg * 2;
#pragma unroll
                for (int hr = 0; hr < 2; ++hr) {
                    const int ml = mbase + f * 16 + hr * 8;
                    const int n2 = 256 + n;
                    float2 xa = *(const float2*)&xaRow[(f * 16 + hr * 8) * NSd + n2];
                    __half2 hh = __floats2half2_rn(tanh_ap(xa.x + acc[f][g][hr * 2 + 0]),
                                                   tanh_ap(xa.y + acc[f][g][hr * 2 + 1]));
                    const float zx = __low2float(hh), zy = __high2float(hh);
                    __half2 zp = *(__half2*)&smh[ml * Z_LDH + n2];
                    const float dx = zx - __low2float(zp);
                    const float dy = zy - __high2float(zp);
                    lnum += dx * dx + dy * dy;
                    lden += zx * zx + zy * zy;
                    *(__half2*)&smh[ml * Z_LDH + n2] = hh;
                    *(__half2*)&smh[ml * Z_LDH + n] =
                        *reinterpret_cast<__half2*>(&stash[(f * 4 + g) * 2 + hr]);
                }
            }
        }

        float2 bpart = block_reduce2(lnum, lden);
        if (tid == 0) {
            g_part[t & 1][2 * blockIdx.x]     = bpart.x;
            g_part[t & 1][2 * blockIdx.x + 1] = bpart.y;
            __threadfence();
            if (t > 2) {
                while (g_ecnt[t - 1] < (unsigned)GRID_IT) { }
                __threadfence();
            }
        }
        __syncthreads();

        bool stop = false;
        if (t > 2) {
            float pn = 0.f, pd = 0.f;
            if (tid < GRID_IT) {
                float2 pp = __ldcg((const float2*)&g_part[(t - 1) & 1][2 * tid]);
                pn = pp.x; pd = pp.y;
            }
            float2 tot = block_reduce2(pn, pd);
            const float res = sqrtf(tot.x) / (sqrtf(tot.y) + 1e-8f);
            stop = (res <= EPS_STOP);
        }
        __syncthreads();
        if (tid == 0) atomicAdd((unsigned*)(g_ecnt + t), 1u);
        if (stop) break;
    }

    // Discard the speculative g_Bblk chunk-0 preload: consume its arrival.
    MBAR_WAIT(mb, ph0 & 1); ph0++;

    // ---- y = z* @ Wh^T + bh (hi/lo split), written directly to out ----
    // y-lo preloads BTblk chunk 0 so the vjp starts hot.
    {
        float yacc[4][4];
        mma_pass_y<true >(zb, g_Whb, g_Whb + (size_t)8 * CHY_HALF, CHY_BYTES, false,
                          bb, mb, ph0, ph1, yacc);
        mma_pass_y<false>(zb, g_Whb + (size_t)8 * CHY_HALF, g_BTblk, CH_BYTES, true,
                          bb, mb, ph0, ph1, yacc);
        const int wm = w >> 1, wn = w & 1;
#pragma unroll
        for (int g = 0; g < 4; ++g) {
            const int col = wn * 32 + g * 8 + tg * 2;
            float2 b2 = *(const float2*)&bhv[col];
#pragma unroll
            for (int hr = 0; hr < 2; ++hr) {
                const int m = m0 + wm * 16 + grp + hr * 8;
                *(float2*)&out[(size_t)m * NOUT + col] =
                    make_float2(yacc[g][hr * 2] + b2.x, yacc[g][hr * 2 + 1] + b2.y);
            }
        }
    }

    // ---- g = v * (1 - z*^2) elementwise (fixed-point identity), overwriting z ----
    __syncthreads();   // y-pass GEMM reads of z complete
    {
        const int npairs = (128 * NSd) / 2;
        for (int i = tid; i < npairs; i += NTH_IT) {
            const int row = i >> 8;
            const int cp = i & 255;
            __half2 zz = *(__half2*)&smh[row * Z_LDH + cp * 2];
            float2 vv = *(const float2*)&v[(size_t)(m0 + row) * NSd + cp * 2];
            const float zx = __low2float(zz), zy = __high2float(zz);
            *(__half2*)&smh[row * Z_LDH + cp * 2] =
                __floats2half2_rn(vv.x * (1.f - zx * zx), vv.y * (1.f - zy * zy));
        }
    }

    // ---- vjp: vJ = g @ Bm ; sum of squares ----
    float ls = 0.f;
    mma_pass<NCHUNK, true>(zb, Z_LDH * 2, g_BTblk,
                           g_BTblk + (size_t)8 * CH_HALF, CH_BYTES, true,
                           bb, mb, ph0, ph1, acc);
#pragma unroll
    for (int f = 0; f < 4; ++f)
#pragma unroll
        for (int g = 0; g < 4; ++g)
#pragma unroll
            for (int r = 0; r < 4; ++r) ls += acc[f][g][r] * acc[f][g][r];
    mma_pass<NCHUNK, false>(zb, Z_LDH * 2, g_BTblk + (size_t)8 * CH_HALF,
                            (const __half*)0, 0, true,
                            bb, mb, ph0, ph1, acc);
#pragma unroll
    for (int f = 0; f < 4; ++f)
#pragma unroll
        for (int g = 0; g < 4; ++g)
#pragma unroll
            for (int r = 0; r < 4; ++r) ls += acc[f][g][r] * acc[f][g][r];

    float2 bs = block_reduce2(ls, 0.f);
    if (tid == 0) {
        g_jacpart[blockIdx.x] = bs.x;
        __threadfence();
        atomicAdd((unsigned*)(g_ecnt + 254), 1u);
    }

    // ---- CTA 0 finalizes jac_loss ----
    if (blockIdx.x == 0) {
        if (tid == 0) {
            while (g_ecnt[254] < (unsigned)GRID_IT) { }
            __threadfence();
        }
        __syncthreads();
        float s = (tid < GRID_IT) ? __ldcg((const float*)&g_jacpart[tid]) : 0.f;
        float2 tt = block_reduce2(s, 0.f);
        if (tid == 0) out[(size_t)NM * NOUT] = tt.x / ((float)NM * (float)NSd);
    }
}

// ---------------- launcher ----------------
extern "C" void kernel_launch(void* const* d_in, const int* in_sizes, int n_in,
                              void* d_out, int out_size) {
    const float* x   = (const float*)d_in[0];
    const float* A   = (const float*)d_in[1];
    const float* Bm  = (const float*)d_in[2];
    const float* b   = (const float*)d_in[3];
    const float* Wh  = (const float*)d_in[4];
    const float* bh  = (const float*)d_in[5];
    const float* v   = (const float*)d_in[6];
    float* out = (float*)d_out;

    static int configured = 0;
    if (!configured) {
        cudaFuncSetAttribute(k_iter, cudaFuncAttributeMaxDynamicSharedMemorySize, SMEM_DYN);
        configured = 1;
    }

    k_prep<<<4096, 256>>>(x, Bm, A, Wh);
    k_iter<<<GRID_IT, NTH_IT, SMEM_DYN>>>(b, v, bh, out);
}